// round 6
// baseline (speedup 1.0000x reference)
#include <cuda_runtime.h>
#include <math.h>

// ---------------- problem constants ----------------
#define B_    2
#define D96   96
#define H_    192
#define W_    192
#define HW_   (H_*W_)        // 36864
#define HEADS 2
#define C48   48
#define HL_   24
#define WL_   24
#define PL_   (HL_*WL_)      // 576
#define QC_   288            // 3*D

// ---------------- scratch (static, no runtime alloc) ----------------
__device__ float g_feats  [(size_t)B_*QC_*HW_];   // concat buffer: slots x0,x1,x2
__device__ float g_qkvfull[(size_t)B_*QC_*HW_];   // full-res qkv conv output
__device__ float g_bufA   [(size_t)B_*D96*HW_];   // MKW conv out
__device__ float g_weff   [D96*D96*9];
__device__ float g_beff   [D96];
__device__ float g_pool   [(size_t)B_*QC_*PL_];
__device__ float g_dw     [(size_t)B_*QC_*PL_];
__device__ float g_attn   [B_*HEADS*C48*C48];
__device__ float g_acomb  [B_*HEADS*C48*C48];
__device__ float g_low1   [(size_t)B_*D96*PL_];
__device__ float g_low2   [(size_t)B_*D96*PL_];
__device__ float g_xk     [(size_t)B_*C48*HW_];   // full-res xk (EAF_LF) / low-res xk (EAF_HF)
__device__ float g_yq     [(size_t)B_*C48*HW_];
__device__ float g_bnx    [2*C48];                // mean[0..47], invstd[48..95]
__device__ float g_bny    [2*C48];
__device__ float g_bnpartA[C48][16][2];
__device__ float g_bnpartB[C48][16][2];

// ---------------- MKW effective weight ----------------
__global__ void build_weight(const float* __restrict__ w,  const float* __restrict__ wc,
                             const float* __restrict__ wh, const float* __restrict__ wv,
                             const float* __restrict__ wa, const float* __restrict__ s4,
                             float* __restrict__ weff) {
    int idx = blockIdx.x * blockDim.x + threadIdx.x;   // oc*96+ic
    if (idx >= D96*D96) return;
    const float s0=s4[0], s1=s4[1], s2=s4[2], s3=s4[3];
    float wcl[9], wal[9];
    float csum = 0.f;
    #pragma unroll
    for (int t=0;t<9;t++){ wcl[t]=wc[(size_t)idx*9+t]; csum+=wcl[t]; }
    #pragma unroll
    for (int t=0;t<9;t++){ wal[t]=wa[(size_t)idx*9+t]; }
    const int perm[9] = {3,0,1,6,4,2,7,8,5};
    float wh0=wh[(size_t)idx*3+0], wh1=wh[(size_t)idx*3+1], wh2=wh[(size_t)idx*3+2];
    float wv0=wv[(size_t)idx*3+0], wv1=wv[(size_t)idx*3+1], wv2=wv[(size_t)idx*3+2];
    #pragma unroll
    for (int t=0;t<9;t++){
        float wcd = wcl[t] - (t==4 ? csum : 0.f);
        float whd = 0.f;
        if (t==0) whd =  wh0; else if (t==3) whd =  wh1; else if (t==6) whd =  wh2;
        else if (t==2) whd = -wh0; else if (t==5) whd = -wh1; else if (t==8) whd = -wh2;
        float wvd = 0.f;
        if (t<3) wvd = (t==0?wv0:(t==1?wv1:wv2));
        else if (t>=6) wvd = -(t==6?wv0:(t==7?wv1:wv2));
        float wad = wal[t] - wal[perm[t]];
        weff[(size_t)idx*9+t] = w[(size_t)idx*9+t] + s0*wcd + s1*whd + s2*wvd + s3*wad;
    }
}

__global__ void build_bias(const float* b, const float* bc, const float* bh,
                           const float* bv, const float* ba, const float* s4,
                           float* beff) {
    int c = threadIdx.x;
    if (c >= D96) return;
    beff[c] = b[c] + s4[0]*bc[c] + s4[1]*bh[c] + s4[2]*bv[c] + s4[3]*ba[c];
}

// ---------------- direct 3x3 conv, pad=1, vectorized-LDS version ----------------
// tile: 32x32 px, 8 oc. block (8,32): tx->4px in x, ty->row.
// grid: (W/32, H/32, B * OC/8)
#define C3_ROWSTR 40                 // smem row stride in floats (16B-aligned rows)
#define C3_ELEMS  (34*34)            // 1156 halo elements
__global__ __launch_bounds__(256, 3)
void conv3x3_kernel(const float* __restrict__ in, long inB, int IC,
                    const float* __restrict__ w, const float* __restrict__ bias,
                    float* __restrict__ out, long outB, int OC) {
    const int tx = threadIdx.x;          // 0..7  -> pixels 4tx..4tx+3
    const int ty = threadIdx.y;          // 0..31 -> output row
    const int tid = ty*8 + tx;
    const int w0 = blockIdx.x * 32;
    const int h0 = blockIdx.y * 32;
    const int nOcg = OC >> 3;
    const int oc0 = (blockIdx.z % nOcg) * 8;
    const int b   =  blockIdx.z / nOcg;

    __shared__ float s_in[2][34*C3_ROWSTR];
    __shared__ float s_w [2][96];        // [8 oc][3 rows][4] (w3r,w3r+1,w3r+2,pad)

    float acc[8][4];
    #pragma unroll
    for (int o=0;o<8;o++)
        #pragma unroll
        for (int p=0;p<4;p++) acc[o][p]=0.f;

    const float* inb = in + (long)b*inB;

    // per-thread gmem->smem geometry (constant over ic)
    int  loff[5], sstore[5];
    bool lval[5];
    #pragma unroll
    for (int s=0;s<5;s++){
        int idx = tid + s*256;
        bool inr = idx < C3_ELEMS;
        int rr = idx / 34, cc = idx % 34;
        int gh = h0 + rr - 1, gw = w0 + cc - 1;
        bool ok = inr && gh >= 0 && gh < H_ && gw >= 0 && gw < W_;
        lval[s]   = ok;
        loff[s]   = ok ? (gh*W_ + gw) : 0;
        sstore[s] = inr ? (rr*C3_ROWSTR + cc) : -1;
    }
    // weight loader: tid<96 -> o=tid/12, r=(tid%12)/4, t=tid%4
    const bool wload = tid < 96;
    long wgoff = 0; bool wreal = false;
    if (wload){
        int o = tid / 12, rem = tid % 12, r = rem / 4, t = rem % 4;
        wreal = (t < 3);
        wgoff = (long)(oc0+o)*IC*9 + r*3 + t;   // +ic*9 added per iter
    }

    // prologue: ic=0 -> buffer 0
    #pragma unroll
    for (int s=0;s<5;s++){
        if (sstore[s] >= 0) s_in[0][sstore[s]] = lval[s] ? inb[loff[s]] : 0.f;
    }
    if (wload) s_w[0][tid] = wreal ? w[wgoff] : 0.f;
    __syncthreads();

    for (int ic=0; ic<IC; ic++){
        const int cur = ic & 1, nxt = cur ^ 1;

        float stage[5]; float wstage = 0.f;
        const bool more = (ic+1 < IC);
        if (more){
            const float* incn = inb + (long)(ic+1)*HW_;
            #pragma unroll
            for (int s=0;s<5;s++) stage[s] = lval[s] ? incn[loff[s]] : 0.f;
            if (wload && wreal) wstage = w[wgoff + (long)(ic+1)*9];
        }

        // compute: 3 input rows, vector loads
        #pragma unroll
        for (int r=0;r<3;r++){
            const float* rowp = &s_in[cur][(ty + r)*C3_ROWSTR + 4*tx];
            float4 xa = *reinterpret_cast<const float4*>(rowp);
            float4 xb = *reinterpret_cast<const float4*>(rowp + 4);
            float xr[8] = {xa.x,xa.y,xa.z,xa.w,xb.x,xb.y,xb.z,xb.w};
            #pragma unroll
            for (int o=0;o<8;o++){
                float4 wq = *reinterpret_cast<const float4*>(&s_w[cur][o*12 + r*4]);
                #pragma unroll
                for (int p=0;p<4;p++){
                    acc[o][p] += xr[p]*wq.x + xr[p+1]*wq.y + xr[p+2]*wq.z;
                }
            }
        }

        if (more){
            #pragma unroll
            for (int s=0;s<5;s++){
                if (sstore[s] >= 0) s_in[nxt][sstore[s]] = stage[s];
            }
            if (wload) s_w[nxt][tid] = wreal ? wstage : 0.f;
        }
        __syncthreads();
    }

    // write 4px per oc with one STG.128
    #pragma unroll
    for (int o=0;o<8;o++){
        float bv = bias[oc0+o];
        float4 r4 = make_float4(acc[o][0]+bv, acc[o][1]+bv, acc[o][2]+bv, acc[o][3]+bv);
        *reinterpret_cast<float4*>(
            &out[(long)b*outB + (long)(oc0+o)*HW_ + (long)(h0+ty)*W_ + (w0+4*tx)]) = r4;
    }
}

// ---------------- 1x1 conv: 512px x 32oc block tile, 16px x 4oc per thread ----------------
// grid: (ceil(npix/512), ceil(OC/32), B); block 256. IC % 16 == 0, npix % 4 == 0.
__global__ __launch_bounds__(256, 2)
void conv1x1_kernel(const float* __restrict__ in, long inB, int IC,
                    const float* __restrict__ w, const float* __restrict__ bias,
                    float* __restrict__ out, long outB, int OC, int npix) {
    const int tid  = threadIdx.x;
    const int lane = tid & 31;
    const int wy   = tid >> 5;           // warp id 0..7 -> 4 oc each
    const int p0   = blockIdx.x * 512;
    const int oc0  = blockIdx.y * 32;
    const int b    = blockIdx.z;

    __shared__ float xs[16][512];
    __shared__ float ws[16][32];

    float4 acc[4][4];                    // [oc j][px quad q]
    #pragma unroll
    for (int j=0;j<4;j++)
        #pragma unroll
        for (int q=0;q<4;q++) acc[j][q] = make_float4(0.f,0.f,0.f,0.f);

    const float* inb = in + (long)b*inB;

    for (int c0=0; c0<IC; c0+=16) {
        #pragma unroll
        for (int s=0;s<8;s++){
            int li  = tid + s*256;
            int icl = li >> 7, pq = li & 127;
            int p = p0 + pq*4;
            float4 v = make_float4(0.f,0.f,0.f,0.f);
            if (p < npix)
                v = *reinterpret_cast<const float4*>(&inb[(long)(c0+icl)*npix + p]);
            *reinterpret_cast<float4*>(&xs[icl][pq*4]) = v;
        }
        #pragma unroll
        for (int s=0;s<2;s++){
            int li  = tid + s*256;
            int icl = li >> 5, ocl = li & 31;
            float v = 0.f;
            if (oc0+ocl < OC) v = w[(long)(oc0+ocl)*IC + (c0+icl)];
            ws[icl][ocl] = v;
        }
        __syncthreads();
        #pragma unroll
        for (int ic=0; ic<16; ic++) {
            float4 xv[4];
            #pragma unroll
            for (int q=0;q<4;q++) xv[q] = *reinterpret_cast<const float4*>(&xs[ic][(q*32+lane)*4]);
            float4 wv = *reinterpret_cast<const float4*>(&ws[ic][wy*4]);
            #pragma unroll
            for (int q=0;q<4;q++){
                acc[0][q].x += xv[q].x*wv.x; acc[0][q].y += xv[q].y*wv.x; acc[0][q].z += xv[q].z*wv.x; acc[0][q].w += xv[q].w*wv.x;
                acc[1][q].x += xv[q].x*wv.y; acc[1][q].y += xv[q].y*wv.y; acc[1][q].z += xv[q].z*wv.y; acc[1][q].w += xv[q].w*wv.y;
                acc[2][q].x += xv[q].x*wv.z; acc[2][q].y += xv[q].y*wv.z; acc[2][q].z += xv[q].z*wv.z; acc[2][q].w += xv[q].w*wv.z;
                acc[3][q].x += xv[q].x*wv.w; acc[3][q].y += xv[q].y*wv.w; acc[3][q].z += xv[q].z*wv.w; acc[3][q].w += xv[q].w*wv.w;
            }
        }
        __syncthreads();
    }

    #pragma unroll
    for (int j=0;j<4;j++){
        int oc = oc0 + wy*4 + j;
        if (oc >= OC) continue;
        float bv = bias ? bias[oc] : 0.f;
        #pragma unroll
        for (int q=0;q<4;q++){
            int p = p0 + (q*32+lane)*4;
            if (p < npix){
                float4 r = acc[j][q];
                r.x += bv; r.y += bv; r.z += bv; r.w += bv;
                *reinterpret_cast<float4*>(&out[(long)b*outB + (long)oc*npix + p]) = r;
            }
        }
    }
}

// ---------------- 8x8 max pool ----------------
__global__ void maxpool8(const float* __restrict__ in, float* __restrict__ out) {
    int idx = blockIdx.x*blockDim.x + threadIdx.x;   // B*288*24*24
    if (idx >= B_*QC_*PL_) return;
    int ow = idx % WL_;
    int oh = (idx / WL_) % HL_;
    int c  = (idx / PL_) % QC_;
    int b  =  idx / (PL_*QC_);
    const float* p = in + ((long)b*QC_ + c)*HW_ + (long)oh*8*W_ + ow*8;
    float m = -INFINITY;
    #pragma unroll
    for (int r=0;r<8;r++)
        #pragma unroll
        for (int cc=0;cc<8;cc++)
            m = fmaxf(m, p[r*W_ + cc]);
    out[idx] = m;
}

// ---------------- depthwise 3x3, pad=1, 24x24 ----------------
__global__ void dwconv3x3(const float* __restrict__ in, const float* __restrict__ w,
                          const float* __restrict__ bias, float* __restrict__ out) {
    int idx = blockIdx.x*blockDim.x + threadIdx.x;   // B*288*576
    if (idx >= B_*QC_*PL_) return;
    int ow = idx % WL_;
    int oh = (idx / WL_) % HL_;
    int c  = (idx / PL_) % QC_;
    int b  =  idx / (PL_*QC_);
    const float* p = in + ((long)b*QC_ + c)*PL_;
    const float* wc = w + (long)c*9;
    float s = bias[c];
    #pragma unroll
    for (int dr=-1;dr<=1;dr++){
        int hh = oh+dr; if (hh<0||hh>=HL_) continue;
        #pragma unroll
        for (int dc=-1;dc<=1;dc++){
            int ww = ow+dc; if (ww<0||ww>=WL_) continue;
            s += wc[(dr+1)*3 + (dc+1)] * p[hh*WL_ + ww];
        }
    }
    out[idx] = s;
}

// ---------------- normalize q / k rows in place ----------------
__global__ void rownorm(float* dw) {
    int rid = blockIdx.x;                 // 0..383
    int sel = rid / (B_*HEADS*C48);       // 0=q, 1=k
    int rem = rid % (B_*HEADS*C48);
    int b   = rem / (HEADS*C48);
    int ch  = rem % (HEADS*C48);
    float* row = dw + ((long)b*QC_ + sel*D96 + ch)*PL_;
    __shared__ float sh[256];
    float s = 0.f;
    for (int i=threadIdx.x;i<PL_;i+=256){ float v=row[i]; s += v*v; }
    sh[threadIdx.x]=s; __syncthreads();
    for (int st=128;st>0;st>>=1){ if (threadIdx.x<st) sh[threadIdx.x]+=sh[threadIdx.x+st]; __syncthreads(); }
    float scale = 1.f / fmaxf(sqrtf(sh[0]), 1e-12f);
    for (int i=threadIdx.x;i<PL_;i+=256) row[i]*=scale;
}

// ---------------- attn = qn @ kn^T * temp ----------------
__global__ void attn_kernel(const float* __restrict__ dw, const float* __restrict__ temp,
                            float* __restrict__ attn) {
    int idx = blockIdx.x*blockDim.x + threadIdx.x;
    if (idx >= B_*HEADS*C48*C48) return;
    int j = idx % C48;
    int i = (idx / C48) % C48;
    int h = (idx / (C48*C48)) % HEADS;
    int b =  idx / (C48*C48*HEADS);
    const float* q = dw + ((long)b*QC_ +      h*C48 + i)*PL_;
    const float* k = dw + ((long)b*QC_ + D96 + h*C48 + j)*PL_;
    float s = 0.f;
    for (int n=0;n<PL_;n++) s += q[n]*k[n];
    attn[idx] = s * temp[h];
}

// ---------------- top-k threshold softmaxes, combined ----------------
__global__ void topk_combine(const float* __restrict__ attn, const float* __restrict__ aw,
                             float* __restrict__ acomb) {
    int r = threadIdx.x;                  // 0..191
    if (r >= B_*HEADS*C48) return;
    const float* row = attn + (long)r*C48;
    float a[C48], srt[C48];
    for (int j=0;j<C48;j++){ a[j]=row[j]; srt[j]=a[j]; }
    for (int x=1;x<C48;x++){
        float key = srt[x]; int j = x-1;
        while (j>=0 && srt[j]<key){ srt[j+1]=srt[j]; j--; }
        srt[j+1]=key;
    }
    const int kks[4] = {24,32,36,38};
    float m = srt[0];
    float th[4], sm[4];
    #pragma unroll
    for (int l=0;l<4;l++){
        th[l] = srt[kks[l]-1];
        float s = 0.f;
        for (int j=0;j<C48;j++) if (a[j] >= th[l]) s += expf(a[j]-m);
        sm[l] = s;
    }
    float w0=aw[0], w1=aw[1], w2=aw[2], w3=aw[3];
    for (int j=0;j<C48;j++){
        float e = expf(a[j]-m);
        float o = 0.f;
        if (a[j] >= th[0]) o += w0*e/sm[0];
        if (a[j] >= th[1]) o += w1*e/sm[1];
        if (a[j] >= th[2]) o += w2*e/sm[2];
        if (a[j] >= th[3]) o += w3*e/sm[3];
        acomb[(long)r*C48 + j] = o;
    }
}

// ---------------- out = gelu(Acomb @ v) ----------------
__global__ void av_gelu(const float* __restrict__ acomb, const float* __restrict__ dw,
                        float* __restrict__ outlow) {
    int idx = blockIdx.x*blockDim.x + threadIdx.x;
    if (idx >= B_*HEADS*C48*PL_) return;
    int n = idx % PL_;
    int c = (idx / PL_) % C48;
    int h = (idx / (PL_*C48)) % HEADS;
    int b =  idx / (PL_*C48*HEADS);
    const float* arow = acomb + (((long)(b*HEADS+h))*C48 + c)*C48;
    const float* v = dw + ((long)b*QC_ + 2*D96 + h*C48)*PL_;
    float s = 0.f;
    #pragma unroll 4
    for (int d=0;d<C48;d++) s += arow[d] * v[(long)d*PL_ + n];
    float g = 0.5f * s * (1.f + erff(s * 0.70710678118654752440f));
    outlow[((long)b*D96 + h*C48 + c)*PL_ + n] = g;
}

// ---------------- BN stats: one full-res 48ch tensor, partials ----------------
__global__ void bn_partial1(const float* __restrict__ src, float (*part)[16][2]) {
    int c = blockIdx.x;       // 0..47
    int chunk = blockIdx.y;   // 0..15
    const float* base = src + ((long)(chunk>>3)*C48 + c)*HW_ + (long)(chunk & 7)*(HW_/8);
    float s = 0.f, s2 = 0.f;
    for (int i = threadIdx.x; i < HW_/8; i += 256){
        float v = base[i]; s += v; s2 += v*v;
    }
    __shared__ float sh[512];
    sh[threadIdx.x] = s; sh[256+threadIdx.x] = s2; __syncthreads();
    for (int st=128; st>0; st>>=1){
        if (threadIdx.x < st){ sh[threadIdx.x]+=sh[threadIdx.x+st]; sh[256+threadIdx.x]+=sh[256+threadIdx.x+st]; }
        __syncthreads();
    }
    if (threadIdx.x == 0){ part[c][chunk][0] = sh[0]; part[c][chunk][1] = sh[256]; }
}

__global__ void bn_final1(const float (*part)[16][2], float* dst) {
    int c = threadIdx.x;      // 0..47
    if (c >= C48) return;
    float s = 0.f, s2 = 0.f;
    #pragma unroll
    for (int k=0;k<16;k++){ s += part[c][k][0]; s2 += part[c][k][1]; }
    float N = (float)(B_*HW_);
    float m = s/N;
    float var = s2/N - m*m;
    dst[c]       = m;
    dst[C48+c]   = rsqrtf(fmaxf(var,0.f) + 1e-5f);
}

// ---------------- BN stats for low-res (exact equivalent of 64x-replicated) ----------------
__global__ void bn_low(const float* __restrict__ src, float* __restrict__ dst) {
    int c = blockIdx.x;       // 0..47
    float s = 0.f, s2 = 0.f;
    for (int i = threadIdx.x; i < B_*PL_; i += 256){
        int b = i / PL_, j = i % PL_;
        float v = src[((long)b*C48 + c)*PL_ + j];
        s += v; s2 += v*v;
    }
    __shared__ float sh[512];
    sh[threadIdx.x]=s; sh[256+threadIdx.x]=s2; __syncthreads();
    for (int st=128; st>0; st>>=1){
        if (threadIdx.x < st){ sh[threadIdx.x]+=sh[threadIdx.x+st]; sh[256+threadIdx.x]+=sh[256+threadIdx.x+st]; }
        __syncthreads();
    }
    if (threadIdx.x == 0){
        float N = (float)(B_*PL_);
        float m = sh[0]/N;
        float var = sh[256]/N - m*m;
        dst[c]     = m;
        dst[C48+c] = rsqrtf(fmaxf(var,0.f) + 1e-5f);
    }
}

// ---------------- EAF blend (both full-res) ----------------
__global__ void eaf_blend(const float* __restrict__ x, long xB,
                          const float* __restrict__ y, long yB,
                          const float* __restrict__ xk, const float* __restrict__ yq,
                          const float* __restrict__ bnx, const float* __restrict__ bny,
                          float* __restrict__ out, long outB) {
    int p = blockIdx.x*blockDim.x + threadIdx.x;
    int b = blockIdx.y;
    if (p >= HW_) return;
    long base = (long)b*C48*HW_ + p;
    float s = 0.f;
    for (int c=0;c<C48;c++){
        float a  = (xk[base + (long)c*HW_] - bnx[c]) * bnx[C48+c];
        float bb = (yq[base + (long)c*HW_] - bny[c]) * bny[C48+c];
        s += a*bb;
    }
    float sim = 1.f/(1.f + expf(-s));
    for (int c=0;c<D96;c++){
        float xv = x[(long)b*xB + (long)c*HW_ + p];
        float yv = y[(long)b*yB + (long)c*HW_ + p];
        out[(long)b*outB + (long)c*HW_ + p] = sim*xv + (1.f-sim)*yv;
    }
}

// ---------------- EAF blend HF variant: x and xk at low res ----------------
__global__ void eaf_blend_hf(const float* __restrict__ xlow,    // [B,96,576]
                             const float* __restrict__ y, long yB,
                             const float* __restrict__ xklow,   // [B,48,576]
                             const float* __restrict__ yq,
                             const float* __restrict__ bnx, const float* __restrict__ bny,
                             float* __restrict__ out, long outB) {
    int p = blockIdx.x*blockDim.x + threadIdx.x;
    int b = blockIdx.y;
    if (p >= HW_) return;
    int h = p / W_, w = p % W_;
    int lp = (h>>3)*WL_ + (w>>3);
    long basey = (long)b*C48*HW_ + p;
    float s = 0.f;
    for (int c=0;c<C48;c++){
        float a  = (xklow[((long)b*C48 + c)*PL_ + lp] - bnx[c]) * bnx[C48+c];
        float bb = (yq[basey + (long)c*HW_] - bny[c]) * bny[C48+c];
        s += a*bb;
    }
    float sim = 1.f/(1.f + expf(-s));
    for (int c=0;c<D96;c++){
        float xv = xlow[((long)b*D96 + c)*PL_ + lp];
        float yv = y[(long)b*yB + (long)c*HW_ + p];
        out[(long)b*outB + (long)c*HW_ + p] = sim*xv + (1.f-sim)*yv;
    }
}

// ---------------- copy input into feats slot 0 ----------------
__global__ void copy_slot0(const float* __restrict__ x, float* __restrict__ feats) {
    long idx = (long)blockIdx.x*blockDim.x + threadIdx.x;
    if (idx >= (long)B_*D96*HW_) return;
    long per = (long)D96*HW_;
    int b = idx / per;
    long r = idx % per;
    feats[(long)b*QC_*HW_ + r] = x[idx];
}

// ---------------- orchestration ----------------
extern "C" void kernel_launch(void* const* d_in, const int* in_sizes, int n_in,
                              void* d_out, int out_size) {
    const float* x_in   = (const float*)d_in[0];
    const float* hf     = (const float*)d_in[1];
    const float* lf     = (const float*)d_in[2];
    const float* mkw_w  = (const float*)d_in[3];
    const float* mkw_b  = (const float*)d_in[4];
    const float* mkw_wc = (const float*)d_in[5];
    const float* mkw_bc = (const float*)d_in[6];
    const float* mkw_wh = (const float*)d_in[7];
    const float* mkw_bh = (const float*)d_in[8];
    const float* mkw_wv = (const float*)d_in[9];
    const float* mkw_bv = (const float*)d_in[10];
    const float* mkw_wa = (const float*)d_in[11];
    const float* mkw_ba = (const float*)d_in[12];
    const float* mkw_s  = (const float*)d_in[13];
    const float* dt_temp= (const float*)d_in[14];
    const float* dt_wqkv= (const float*)d_in[15];
    const float* dt_bqkv= (const float*)d_in[16];
    const float* dt_wdw = (const float*)d_in[17];
    const float* dt_bdw = (const float*)d_in[18];
    const float* dt_wprj= (const float*)d_in[19];
    const float* dt_bprj= (const float*)d_in[20];
    const float* dt_aw  = (const float*)d_in[21];
    const float* eh_wx  = (const float*)d_in[22];
    const float* eh_wy  = (const float*)d_in[23];
    const float* el_wx  = (const float*)d_in[24];
    const float* el_wy  = (const float*)d_in[25];
    const float* cab_w  = (const float*)d_in[26];
    const float* cab_b  = (const float*)d_in[27];
    float* out = (float*)d_out;

    float *feats, *qkvfull, *bufA, *weff, *beff, *pool, *dw, *attn, *acomb,
          *low1, *low2, *xk, *yq, *bnx, *bny;
    float (*bnpartA)[16][2]; float (*bnpartB)[16][2];
    cudaGetSymbolAddress((void**)&feats,   g_feats);
    cudaGetSymbolAddress((void**)&qkvfull, g_qkvfull);
    cudaGetSymbolAddress((void**)&bufA,    g_bufA);
    cudaGetSymbolAddress((void**)&weff,    g_weff);
    cudaGetSymbolAddress((void**)&beff,    g_beff);
    cudaGetSymbolAddress((void**)&pool,    g_pool);
    cudaGetSymbolAddress((void**)&dw,      g_dw);
    cudaGetSymbolAddress((void**)&attn,    g_attn);
    cudaGetSymbolAddress((void**)&acomb,   g_acomb);
    cudaGetSymbolAddress((void**)&low1,    g_low1);
    cudaGetSymbolAddress((void**)&low2,    g_low2);
    cudaGetSymbolAddress((void**)&xk,      g_xk);
    cudaGetSymbolAddress((void**)&yq,      g_yq);
    cudaGetSymbolAddress((void**)&bnx,     g_bnx);
    cudaGetSymbolAddress((void**)&bny,     g_bny);
    cudaGetSymbolAddress((void**)&bnpartA, g_bnpartA);
    cudaGetSymbolAddress((void**)&bnpartB, g_bnpartB);

    const long fB   = (long)QC_*HW_;      // feats batch stride
    const long dB   = (long)D96*HW_;      // 96ch full-res batch stride
    const long cB   = (long)C48*HW_;      // 48ch full-res batch stride
    const long lowB = (long)D96*PL_;      // low-res 96ch batch stride
    const long lowC = (long)C48*PL_;      // low-res 48ch batch stride

    {
        long n = (long)B_*D96*HW_;
        copy_slot0<<<(unsigned)((n+255)/256), 256>>>(x_in, feats);
    }

    for (int i=0;i<2;i++){
        const float* s4 = mkw_s + i*4;
        build_weight<<<(D96*D96+255)/256, 256>>>(mkw_w + (size_t)i*D96*D96*9,
                                                 mkw_wc + (size_t)i*D96*D96*9,
                                                 mkw_wh + (size_t)i*D96*D96*3,
                                                 mkw_wv + (size_t)i*D96*D96*3,
                                                 mkw_wa + (size_t)i*D96*D96*9,
                                                 s4, weff);
        build_bias<<<1, D96>>>(mkw_b + i*D96, mkw_bc + i*D96, mkw_bh + i*D96,
                               mkw_bv + i*D96, mkw_ba + i*D96, s4, beff);

        const float* xcur = feats + (size_t)i*D96*HW_;
        conv3x3_kernel<<<dim3(W_/32, H_/32, B_*(D96/8)), dim3(8,32)>>>(
            xcur, fB, D96, weff, beff, bufA, dB, D96);

        // qkv 1x1 (full res)
        conv1x1_kernel<<<dim3(HW_/512, QC_/32, B_), 256>>>(
            bufA, dB, D96, dt_wqkv + (size_t)i*QC_*D96, dt_bqkv + i*QC_,
            qkvfull, fB, QC_, HW_);

        maxpool8<<<(B_*QC_*PL_+255)/256, 256>>>(qkvfull, pool);
        dwconv3x3<<<(B_*QC_*PL_+255)/256, 256>>>(pool, dt_wdw + (size_t)i*QC_*9,
                                                 dt_bdw + i*QC_, dw);
        rownorm<<<2*B_*HEADS*C48, 256>>>(dw);
        attn_kernel<<<(B_*HEADS*C48*C48+255)/256, 256>>>(dw, dt_temp + i*HEADS, attn);
        topk_combine<<<1, 192>>>(attn, dt_aw + i*4, acomb);
        av_gelu<<<(B_*HEADS*C48*PL_+255)/256, 256>>>(acomb, dw, low1);

        // proj 1x1 at low res (commutes with nearest upsample) -> low2 = z (low res)
        conv1x1_kernel<<<dim3((PL_+511)/512, D96/32, B_), 256>>>(
            low1, lowB, D96, dt_wprj + (size_t)i*D96*D96, dt_bprj + i*D96,
            low2, lowB, D96, PL_);

        float* slot_out = feats + (size_t)(i+1)*D96*HW_;

        // ---- EAF_HF: x = upsample(low2); xk = conv(x) == upsample(conv(low2)) ----
        conv1x1_kernel<<<dim3((PL_+511)/512, (C48+31)/32, B_), 256>>>(
            low2, lowB, D96, eh_wx + (size_t)i*C48*D96, nullptr, xk, lowC, C48, PL_);
        conv1x1_kernel<<<dim3(HW_/512, (C48+31)/32, B_), 256>>>(
            hf, dB, D96, eh_wy + (size_t)i*C48*D96, nullptr, yq, cB, C48, HW_);
        bn_low<<<C48, 256>>>(xk, bnx);      // stats of upsampled == stats of low-res
        bn_partial1<<<dim3(C48,16), 256>>>(yq, bnpartB);
        bn_final1<<<1, C48>>>(bnpartB, bny);
        eaf_blend_hf<<<dim3(HW_/256, B_), 256>>>(low2, hf, dB, xk, yq, bnx, bny,
                                                 slot_out, fB);

        // ---- EAF_LF: both full res ----
        conv1x1_kernel<<<dim3(HW_/512, (C48+31)/32, B_), 256>>>(
            slot_out, fB, D96, el_wx + (size_t)i*C48*D96, nullptr, xk, cB, C48, HW_);
        conv1x1_kernel<<<dim3(HW_/512, (C48+31)/32, B_), 256>>>(
            lf, dB, D96, el_wy + (size_t)i*C48*D96, nullptr, yq, cB, C48, HW_);
        bn_partial1<<<dim3(C48,16), 256>>>(xk, bnpartA);
        bn_partial1<<<dim3(C48,16), 256>>>(yq, bnpartB);
        bn_final1<<<1, C48>>>(bnpartA, bnx);
        bn_final1<<<1, C48>>>(bnpartB, bny);
        eaf_blend<<<dim3(HW_/256, B_), 256>>>(slot_out, fB, lf, dB, xk, yq, bnx, bny,
                                              slot_out, fB);
    }

    conv3x3_kernel<<<dim3(W_/32, H_/32, B_*(D96/8)), dim3(8,32)>>>(
        feats, fB, QC_, cab_w, cab_b, out, dB, D96);
}

// round 7
// speedup vs baseline: 1.3986x; 1.3986x over previous
#include <cuda_runtime.h>
#include <math.h>

// ---------------- problem constants ----------------
#define B_    2
#define D96   96
#define H_    192
#define W_    192
#define HW_   (H_*W_)        // 36864
#define HEADS 2
#define C48   48
#define HL_   24
#define WL_   24
#define PL_   (HL_*WL_)      // 576
#define QC_   288            // 3*D
#define NT_   18432          // winograd tiles: 96*96 per image * 2 images

// ---------------- scratch (static, no runtime alloc) ----------------
__device__ float g_feats  [(size_t)B_*QC_*HW_];   // concat buffer: slots x0,x1,x2
__device__ float g_qkvfull[(size_t)B_*QC_*HW_];   // full-res qkv conv output
__device__ float g_bufA   [(size_t)B_*D96*HW_];   // MKW conv out
__device__ float g_weff   [D96*D96*9];
__device__ float g_beff   [D96];
__device__ float g_pool   [(size_t)B_*QC_*PL_];
__device__ float g_dw     [(size_t)B_*QC_*PL_];
__device__ float g_attn   [B_*HEADS*C48*C48];
__device__ float g_acomb  [B_*HEADS*C48*C48];
__device__ float g_low1   [(size_t)B_*D96*PL_];
__device__ float g_low2   [(size_t)B_*D96*PL_];
__device__ float g_xk     [(size_t)B_*C48*HW_];
__device__ float g_yq     [(size_t)B_*C48*HW_];
__device__ float g_bnx    [2*C48];
__device__ float g_bny    [2*C48];
__device__ float g_bnpartA[C48][16][2];
__device__ float g_bnpartB[C48][16][2];
// winograd scratch
__device__ float g_U      [(size_t)16*D96*QC_];          // weight transform (max IC=288)
__device__ float g_V      [(size_t)16*QC_*NT_];          // input transform  (max IC=288)
__device__ float g_M      [(size_t)16*D96*NT_];          // gemm output

// ---------------- MKW effective weight ----------------
__global__ void build_weight(const float* __restrict__ w,  const float* __restrict__ wc,
                             const float* __restrict__ wh, const float* __restrict__ wv,
                             const float* __restrict__ wa, const float* __restrict__ s4,
                             float* __restrict__ weff) {
    int idx = blockIdx.x * blockDim.x + threadIdx.x;   // oc*96+ic
    if (idx >= D96*D96) return;
    const float s0=s4[0], s1=s4[1], s2=s4[2], s3=s4[3];
    float wcl[9], wal[9];
    float csum = 0.f;
    #pragma unroll
    for (int t=0;t<9;t++){ wcl[t]=wc[(size_t)idx*9+t]; csum+=wcl[t]; }
    #pragma unroll
    for (int t=0;t<9;t++){ wal[t]=wa[(size_t)idx*9+t]; }
    const int perm[9] = {3,0,1,6,4,2,7,8,5};
    float wh0=wh[(size_t)idx*3+0], wh1=wh[(size_t)idx*3+1], wh2=wh[(size_t)idx*3+2];
    float wv0=wv[(size_t)idx*3+0], wv1=wv[(size_t)idx*3+1], wv2=wv[(size_t)idx*3+2];
    #pragma unroll
    for (int t=0;t<9;t++){
        float wcd = wcl[t] - (t==4 ? csum : 0.f);
        float whd = 0.f;
        if (t==0) whd =  wh0; else if (t==3) whd =  wh1; else if (t==6) whd =  wh2;
        else if (t==2) whd = -wh0; else if (t==5) whd = -wh1; else if (t==8) whd = -wh2;
        float wvd = 0.f;
        if (t<3) wvd = (t==0?wv0:(t==1?wv1:wv2));
        else if (t>=6) wvd = -(t==6?wv0:(t==7?wv1:wv2));
        float wad = wal[t] - wal[perm[t]];
        weff[(size_t)idx*9+t] = w[(size_t)idx*9+t] + s0*wcd + s1*whd + s2*wvd + s3*wad;
    }
}

__global__ void build_bias(const float* b, const float* bc, const float* bh,
                           const float* bv, const float* ba, const float* s4,
                           float* beff) {
    int c = threadIdx.x;
    if (c >= D96) return;
    beff[c] = b[c] + s4[0]*bc[c] + s4[1]*bh[c] + s4[2]*bv[c] + s4[3]*ba[c];
}

// ---------------- Winograd F(2x2,3x3): weight transform U = G g G^T ----------------
// w: [OC][IC][9] -> U: [16][OC*IC]
__global__ void wino_wtrans(const float* __restrict__ w, int OC, int IC,
                            float* __restrict__ U) {
    int idx = blockIdx.x*blockDim.x + threadIdx.x;   // oc*IC + ic
    if (idx >= OC*IC) return;
    float g[9];
    #pragma unroll
    for (int t=0;t<9;t++) g[t] = w[(size_t)idx*9 + t];
    float Gg[4][3];
    #pragma unroll
    for (int c=0;c<3;c++){
        Gg[0][c] = g[c];
        Gg[1][c] = 0.5f*(g[c] + g[3+c] + g[6+c]);
        Gg[2][c] = 0.5f*(g[c] - g[3+c] + g[6+c]);
        Gg[3][c] = g[6+c];
    }
    long OI = (long)OC*IC;
    #pragma unroll
    for (int r=0;r<4;r++){
        float t0=Gg[r][0], t1=Gg[r][1], t2=Gg[r][2];
        U[(long)(r*4+0)*OI + idx] = t0;
        U[(long)(r*4+1)*OI + idx] = 0.5f*(t0+t1+t2);
        U[(long)(r*4+2)*OI + idx] = 0.5f*(t0-t1+t2);
        U[(long)(r*4+3)*OI + idx] = t2;
    }
}

// ---------------- Winograd input transform V = B^T d B ----------------
// in: [B][IC][192][192] (batch stride inB) -> V: [16][IC][NT_]
__global__ void wino_itrans(const float* __restrict__ in, long inB, int IC,
                            float* __restrict__ V) {
    int n  = blockIdx.x*blockDim.x + threadIdx.x;   // 0..NT_-1 (NT_ % 256 == 0)
    int ic = blockIdx.y;
    int b   = n / (NT_/B_);
    int loc = n % (NT_/B_);
    int ty = loc / 96, tx = loc % 96;
    const float* src = in + (long)b*inB + (long)ic*HW_;
    int h0 = 2*ty - 1, w0 = 2*tx - 1;
    float d[4][4];
    #pragma unroll
    for (int r=0;r<4;r++){
        int hh = h0 + r;
        bool hok = (hh >= 0 && hh < H_);
        #pragma unroll
        for (int c=0;c<4;c++){
            int ww = w0 + c;
            d[r][c] = (hok && ww >= 0 && ww < W_) ? src[hh*W_ + ww] : 0.f;
        }
    }
    float t[4][4];
    #pragma unroll
    for (int c=0;c<4;c++){
        t[0][c] = d[0][c] - d[2][c];
        t[1][c] = d[1][c] + d[2][c];
        t[2][c] = d[2][c] - d[1][c];
        t[3][c] = d[1][c] - d[3][c];
    }
    long stride = (long)IC*NT_;
    long base = (long)ic*NT_ + n;
    #pragma unroll
    for (int r=0;r<4;r++){
        float v0 = t[r][0] - t[r][2];
        float v1 = t[r][1] + t[r][2];
        float v2 = t[r][2] - t[r][1];
        float v3 = t[r][1] - t[r][3];
        V[(long)(r*4+0)*stride + base] = v0;
        V[(long)(r*4+1)*stride + base] = v1;
        V[(long)(r*4+2)*stride + base] = v2;
        V[(long)(r*4+3)*stride + base] = v3;
    }
}

// ---------------- Winograd output transform Y = A^T m A + bias ----------------
// M: [16][96][NT_] -> out: [B][96][192][192] (batch stride outB)
__global__ void wino_otrans(const float* __restrict__ Mm, const float* __restrict__ bias,
                            float* __restrict__ out, long outB) {
    int idx = blockIdx.x*blockDim.x + threadIdx.x;   // oc*NT_ + n
    if (idx >= D96*NT_) return;
    int n  = idx % NT_;
    int oc = idx / NT_;
    float m[4][4];
    #pragma unroll
    for (int p=0;p<16;p++)
        m[p>>2][p&3] = Mm[((long)p*D96 + oc)*NT_ + n];
    float t[2][4];
    #pragma unroll
    for (int c=0;c<4;c++){
        t[0][c] = m[0][c] + m[1][c] + m[2][c];
        t[1][c] = m[1][c] - m[2][c] - m[3][c];
    }
    float bv = bias[oc];
    float y00 = t[0][0] + t[0][1] + t[0][2] + bv;
    float y01 = t[0][1] - t[0][2] - t[0][3] + bv;
    float y10 = t[1][0] + t[1][1] + t[1][2] + bv;
    float y11 = t[1][1] - t[1][2] - t[1][3] + bv;
    int b   = n / (NT_/B_);
    int loc = n % (NT_/B_);
    int ty = loc / 96, tx = loc % 96;
    float* dst = out + (long)b*outB + (long)oc*HW_ + (long)(2*ty)*W_ + 2*tx;
    dst[0]    = y00; dst[1]    = y01;
    dst[W_]   = y10; dst[W_+1] = y11;
}

// ---------------- GEMM / 1x1 conv: 512px x 32oc block tile, 16px x 4oc / thread ----
// grid: (ceil(npix/512), ceil(OC/32), Z); block 256. IC % 16 == 0, npix % 4 == 0.
// z-batch: in += z*inB, out += z*outB, w += z*wB (wB=0 -> shared weights).
__global__ __launch_bounds__(256, 2)
void conv1x1_kernel(const float* __restrict__ in, long inB, int IC,
                    const float* __restrict__ w, const float* __restrict__ bias,
                    float* __restrict__ out, long outB, int OC, int npix, long wB) {
    const int tid  = threadIdx.x;
    const int lane = tid & 31;
    const int wy   = tid >> 5;
    const int p0   = blockIdx.x * 512;
    const int oc0  = blockIdx.y * 32;
    const int z    = blockIdx.z;

    __shared__ float xs[16][512];
    __shared__ float ws[16][32];

    float4 acc[4][4];
    #pragma unroll
    for (int j=0;j<4;j++)
        #pragma unroll
        for (int q=0;q<4;q++) acc[j][q] = make_float4(0.f,0.f,0.f,0.f);

    const float* inb = in + (long)z*inB;
    const float* wz  = w  + (long)z*wB;

    for (int c0=0; c0<IC; c0+=16) {
        #pragma unroll
        for (int s=0;s<8;s++){
            int li  = tid + s*256;
            int icl = li >> 7, pq = li & 127;
            int p = p0 + pq*4;
            float4 v = make_float4(0.f,0.f,0.f,0.f);
            if (p < npix)
                v = *reinterpret_cast<const float4*>(&inb[(long)(c0+icl)*npix + p]);
            *reinterpret_cast<float4*>(&xs[icl][pq*4]) = v;
        }
        #pragma unroll
        for (int s=0;s<2;s++){
            int li  = tid + s*256;
            int icl = li >> 5, ocl = li & 31;
            float v = 0.f;
            if (oc0+ocl < OC) v = wz[(long)(oc0+ocl)*IC + (c0+icl)];
            ws[icl][ocl] = v;
        }
        __syncthreads();
        #pragma unroll
        for (int ic=0; ic<16; ic++) {
            float4 xv[4];
            #pragma unroll
            for (int q=0;q<4;q++) xv[q] = *reinterpret_cast<const float4*>(&xs[ic][(q*32+lane)*4]);
            float4 wv = *reinterpret_cast<const float4*>(&ws[ic][wy*4]);
            #pragma unroll
            for (int q=0;q<4;q++){
                acc[0][q].x += xv[q].x*wv.x; acc[0][q].y += xv[q].y*wv.x; acc[0][q].z += xv[q].z*wv.x; acc[0][q].w += xv[q].w*wv.x;
                acc[1][q].x += xv[q].x*wv.y; acc[1][q].y += xv[q].y*wv.y; acc[1][q].z += xv[q].z*wv.y; acc[1][q].w += xv[q].w*wv.y;
                acc[2][q].x += xv[q].x*wv.z; acc[2][q].y += xv[q].y*wv.z; acc[2][q].z += xv[q].z*wv.z; acc[2][q].w += xv[q].w*wv.z;
                acc[3][q].x += xv[q].x*wv.w; acc[3][q].y += xv[q].y*wv.w; acc[3][q].z += xv[q].z*wv.w; acc[3][q].w += xv[q].w*wv.w;
            }
        }
        __syncthreads();
    }

    #pragma unroll
    for (int j=0;j<4;j++){
        int oc = oc0 + wy*4 + j;
        if (oc >= OC) continue;
        float bv = bias ? bias[oc] : 0.f;
        #pragma unroll
        for (int q=0;q<4;q++){
            int p = p0 + (q*32+lane)*4;
            if (p < npix){
                float4 r = acc[j][q];
                r.x += bv; r.y += bv; r.z += bv; r.w += bv;
                *reinterpret_cast<float4*>(&out[(long)z*outB + (long)oc*npix + p]) = r;
            }
        }
    }
}

// ---------------- 8x8 max pool ----------------
__global__ void maxpool8(const float* __restrict__ in, float* __restrict__ out) {
    int idx = blockIdx.x*blockDim.x + threadIdx.x;
    if (idx >= B_*QC_*PL_) return;
    int ow = idx % WL_;
    int oh = (idx / WL_) % HL_;
    int c  = (idx / PL_) % QC_;
    int b  =  idx / (PL_*QC_);
    const float* p = in + ((long)b*QC_ + c)*HW_ + (long)oh*8*W_ + ow*8;
    float m = -INFINITY;
    #pragma unroll
    for (int r=0;r<8;r++)
        #pragma unroll
        for (int cc=0;cc<8;cc++)
            m = fmaxf(m, p[r*W_ + cc]);
    out[idx] = m;
}

// ---------------- depthwise 3x3, pad=1, 24x24 ----------------
__global__ void dwconv3x3(const float* __restrict__ in, const float* __restrict__ w,
                          const float* __restrict__ bias, float* __restrict__ out) {
    int idx = blockIdx.x*blockDim.x + threadIdx.x;
    if (idx >= B_*QC_*PL_) return;
    int ow = idx % WL_;
    int oh = (idx / WL_) % HL_;
    int c  = (idx / PL_) % QC_;
    int b  =  idx / (PL_*QC_);
    const float* p = in + ((long)b*QC_ + c)*PL_;
    const float* wc = w + (long)c*9;
    float s = bias[c];
    #pragma unroll
    for (int dr=-1;dr<=1;dr++){
        int hh = oh+dr; if (hh<0||hh>=HL_) continue;
        #pragma unroll
        for (int dc=-1;dc<=1;dc++){
            int ww = ow+dc; if (ww<0||ww>=WL_) continue;
            s += wc[(dr+1)*3 + (dc+1)] * p[hh*WL_ + ww];
        }
    }
    out[idx] = s;
}

// ---------------- normalize q / k rows in place ----------------
__global__ void rownorm(float* dw) {
    int rid = blockIdx.x;
    int sel = rid / (B_*HEADS*C48);
    int rem = rid % (B_*HEADS*C48);
    int b   = rem / (HEADS*C48);
    int ch  = rem % (HEADS*C48);
    float* row = dw + ((long)b*QC_ + sel*D96 + ch)*PL_;
    __shared__ float sh[256];
    float s = 0.f;
    for (int i=threadIdx.x;i<PL_;i+=256){ float v=row[i]; s += v*v; }
    sh[threadIdx.x]=s; __syncthreads();
    for (int st=128;st>0;st>>=1){ if (threadIdx.x<st) sh[threadIdx.x]+=sh[threadIdx.x+st]; __syncthreads(); }
    float scale = 1.f / fmaxf(sqrtf(sh[0]), 1e-12f);
    for (int i=threadIdx.x;i<PL_;i+=256) row[i]*=scale;
}

// ---------------- attn = qn @ kn^T * temp ----------------
__global__ void attn_kernel(const float* __restrict__ dw, const float* __restrict__ temp,
                            float* __restrict__ attn) {
    int idx = blockIdx.x*blockDim.x + threadIdx.x;
    if (idx >= B_*HEADS*C48*C48) return;
    int j = idx % C48;
    int i = (idx / C48) % C48;
    int h = (idx / (C48*C48)) % HEADS;
    int b =  idx / (C48*C48*HEADS);
    const float* q = dw + ((long)b*QC_ +      h*C48 + i)*PL_;
    const float* k = dw + ((long)b*QC_ + D96 + h*C48 + j)*PL_;
    float s = 0.f;
    for (int n=0;n<PL_;n++) s += q[n]*k[n];
    attn[idx] = s * temp[h];
}

// ---------------- top-k threshold softmaxes, combined ----------------
__global__ void topk_combine(const float* __restrict__ attn, const float* __restrict__ aw,
                             float* __restrict__ acomb) {
    int r = threadIdx.x;
    if (r >= B_*HEADS*C48) return;
    const float* row = attn + (long)r*C48;
    float a[C48], srt[C48];
    for (int j=0;j<C48;j++){ a[j]=row[j]; srt[j]=a[j]; }
    for (int x=1;x<C48;x++){
        float key = srt[x]; int j = x-1;
        while (j>=0 && srt[j]<key){ srt[j+1]=srt[j]; j--; }
        srt[j+1]=key;
    }
    const int kks[4] = {24,32,36,38};
    float m = srt[0];
    float th[4], sm[4];
    #pragma unroll
    for (int l=0;l<4;l++){
        th[l] = srt[kks[l]-1];
        float s = 0.f;
        for (int j=0;j<C48;j++) if (a[j] >= th[l]) s += expf(a[j]-m);
        sm[l] = s;
    }
    float w0=aw[0], w1=aw[1], w2=aw[2], w3=aw[3];
    for (int j=0;j<C48;j++){
        float e = expf(a[j]-m);
        float o = 0.f;
        if (a[j] >= th[0]) o += w0*e/sm[0];
        if (a[j] >= th[1]) o += w1*e/sm[1];
        if (a[j] >= th[2]) o += w2*e/sm[2];
        if (a[j] >= th[3]) o += w3*e/sm[3];
        acomb[(long)r*C48 + j] = o;
    }
}

// ---------------- out = gelu(Acomb @ v) ----------------
__global__ void av_gelu(const float* __restrict__ acomb, const float* __restrict__ dw,
                        float* __restrict__ outlow) {
    int idx = blockIdx.x*blockDim.x + threadIdx.x;
    if (idx >= B_*HEADS*C48*PL_) return;
    int n = idx % PL_;
    int c = (idx / PL_) % C48;
    int h = (idx / (PL_*C48)) % HEADS;
    int b =  idx / (PL_*C48*HEADS);
    const float* arow = acomb + (((long)(b*HEADS+h))*C48 + c)*C48;
    const float* v = dw + ((long)b*QC_ + 2*D96 + h*C48)*PL_;
    float s = 0.f;
    #pragma unroll 4
    for (int d=0;d<C48;d++) s += arow[d] * v[(long)d*PL_ + n];
    float g = 0.5f * s * (1.f + erff(s * 0.70710678118654752440f));
    outlow[((long)b*D96 + h*C48 + c)*PL_ + n] = g;
}

// ---------------- BN stats: one full-res 48ch tensor, partials ----------------
__global__ void bn_partial1(const float* __restrict__ src, float (*part)[16][2]) {
    int c = blockIdx.x;
    int chunk = blockIdx.y;
    const float* base = src + ((long)(chunk>>3)*C48 + c)*HW_ + (long)(chunk & 7)*(HW_/8);
    float s = 0.f, s2 = 0.f;
    for (int i = threadIdx.x; i < HW_/8; i += 256){
        float v = base[i]; s += v; s2 += v*v;
    }
    __shared__ float sh[512];
    sh[threadIdx.x] = s; sh[256+threadIdx.x] = s2; __syncthreads();
    for (int st=128; st>0; st>>=1){
        if (threadIdx.x < st){ sh[threadIdx.x]+=sh[threadIdx.x+st]; sh[256+threadIdx.x]+=sh[256+threadIdx.x+st]; }
        __syncthreads();
    }
    if (threadIdx.x == 0){ part[c][chunk][0] = sh[0]; part[c][chunk][1] = sh[256]; }
}

__global__ void bn_final1(const float (*part)[16][2], float* dst) {
    int c = threadIdx.x;
    if (c >= C48) return;
    float s = 0.f, s2 = 0.f;
    #pragma unroll
    for (int k=0;k<16;k++){ s += part[c][k][0]; s2 += part[c][k][1]; }
    float N = (float)(B_*HW_);
    float m = s/N;
    float var = s2/N - m*m;
    dst[c]       = m;
    dst[C48+c]   = rsqrtf(fmaxf(var,0.f) + 1e-5f);
}

// ---------------- BN stats for low-res (exact equivalent of 64x-replicated) ----------------
__global__ void bn_low(const float* __restrict__ src, float* __restrict__ dst) {
    int c = blockIdx.x;
    float s = 0.f, s2 = 0.f;
    for (int i = threadIdx.x; i < B_*PL_; i += 256){
        int b = i / PL_, j = i % PL_;
        float v = src[((long)b*C48 + c)*PL_ + j];
        s += v; s2 += v*v;
    }
    __shared__ float sh[512];
    sh[threadIdx.x]=s; sh[256+threadIdx.x]=s2; __syncthreads();
    for (int st=128; st>0; st>>=1){
        if (threadIdx.x < st){ sh[threadIdx.x]+=sh[threadIdx.x+st]; sh[256+threadIdx.x]+=sh[256+threadIdx.x+st]; }
        __syncthreads();
    }
    if (threadIdx.x == 0){
        float N = (float)(B_*PL_);
        float m = sh[0]/N;
        float var = sh[256]/N - m*m;
        dst[c]     = m;
        dst[C48+c] = rsqrtf(fmaxf(var,0.f) + 1e-5f);
    }
}

// ---------------- EAF blend (both full-res) ----------------
__global__ void eaf_blend(const float* __restrict__ x, long xB,
                          const float* __restrict__ y, long yB,
                          const float* __restrict__ xk, const float* __restrict__ yq,
                          const float* __restrict__ bnx, const float* __restrict__ bny,
                          float* __restrict__ out, long outB) {
    int p = blockIdx.x*blockDim.x + threadIdx.x;
    int b = blockIdx.y;
    if (p >= HW_) return;
    long base = (long)b*C48*HW_ + p;
    float s = 0.f;
    for (int c=0;c<C48;c++){
        float a  = (xk[base + (long)c*HW_] - bnx[c]) * bnx[C48+c];
        float bb = (yq[base + (long)c*HW_] - bny[c]) * bny[C48+c];
        s += a*bb;
    }
    float sim = 1.f/(1.f + expf(-s));
    for (int c=0;c<D96;c++){
        float xv = x[(long)b*xB + (long)c*HW_ + p];
        float yv = y[(long)b*yB + (long)c*HW_ + p];
        out[(long)b*outB + (long)c*HW_ + p] = sim*xv + (1.f-sim)*yv;
    }
}

// ---------------- EAF blend HF variant: x and xk at low res ----------------
__global__ void eaf_blend_hf(const float* __restrict__ xlow,
                             const float* __restrict__ y, long yB,
                             const float* __restrict__ xklow,
                             const float* __restrict__ yq,
                             const float* __restrict__ bnx, const float* __restrict__ bny,
                             float* __restrict__ out, long outB) {
    int p = blockIdx.x*blockDim.x + threadIdx.x;
    int b = blockIdx.y;
    if (p >= HW_) return;
    int h = p / W_, w = p % W_;
    int lp = (h>>3)*WL_ + (w>>3);
    long basey = (long)b*C48*HW_ + p;
    float s = 0.f;
    for (int c=0;c<C48;c++){
        float a  = (xklow[((long)b*C48 + c)*PL_ + lp] - bnx[c]) * bnx[C48+c];
        float bb = (yq[basey + (long)c*HW_] - bny[c]) * bny[C48+c];
        s += a*bb;
    }
    float sim = 1.f/(1.f + expf(-s));
    for (int c=0;c<D96;c++){
        float xv = xlow[((long)b*D96 + c)*PL_ + lp];
        float yv = y[(long)b*yB + (long)c*HW_ + p];
        out[(long)b*outB + (long)c*HW_ + p] = sim*xv + (1.f-sim)*yv;
    }
}

// ---------------- copy input into feats slot 0 ----------------
__global__ void copy_slot0(const float* __restrict__ x, float* __restrict__ feats) {
    long idx = (long)blockIdx.x*blockDim.x + threadIdx.x;
    if (idx >= (long)B_*D96*HW_) return;
    long per = (long)D96*HW_;
    int b = idx / per;
    long r = idx % per;
    feats[(long)b*QC_*HW_ + r] = x[idx];
}

// ---------------- orchestration ----------------
extern "C" void kernel_launch(void* const* d_in, const int* in_sizes, int n_in,
                              void* d_out, int out_size) {
    const float* x_in   = (const float*)d_in[0];
    const float* hf     = (const float*)d_in[1];
    const float* lf     = (const float*)d_in[2];
    const float* mkw_w  = (const float*)d_in[3];
    const float* mkw_b  = (const float*)d_in[4];
    const float* mkw_wc = (const float*)d_in[5];
    const float* mkw_bc = (const float*)d_in[6];
    const float* mkw_wh = (const float*)d_in[7];
    const float* mkw_bh = (const float*)d_in[8];
    const float* mkw_wv = (const float*)d_in[9];
    const float* mkw_bv = (const float*)d_in[10];
    const float* mkw_wa = (const float*)d_in[11];
    const float* mkw_ba = (const float*)d_in[12];
    const float* mkw_s  = (const float*)d_in[13];
    const float* dt_temp= (const float*)d_in[14];
    const float* dt_wqkv= (const float*)d_in[15];
    const float* dt_bqkv= (const float*)d_in[16];
    const float* dt_wdw = (const float*)d_in[17];
    const float* dt_bdw = (const float*)d_in[18];
    const float* dt_wprj= (const float*)d_in[19];
    const float* dt_bprj= (const float*)d_in[20];
    const float* dt_aw  = (const float*)d_in[21];
    const float* eh_wx  = (const float*)d_in[22];
    const float* eh_wy  = (const float*)d_in[23];
    const float* el_wx  = (const float*)d_in[24];
    const float* el_wy  = (const float*)d_in[25];
    const float* cab_w  = (const float*)d_in[26];
    const float* cab_b  = (const float*)d_in[27];
    float* out = (float*)d_out;

    float *feats, *qkvfull, *bufA, *weff, *beff, *pool, *dw, *attn, *acomb,
          *low1, *low2, *xk, *yq, *bnx, *bny, *U, *V, *M;
    float (*bnpartA)[16][2]; float (*bnpartB)[16][2];
    cudaGetSymbolAddress((void**)&feats,   g_feats);
    cudaGetSymbolAddress((void**)&qkvfull, g_qkvfull);
    cudaGetSymbolAddress((void**)&bufA,    g_bufA);
    cudaGetSymbolAddress((void**)&weff,    g_weff);
    cudaGetSymbolAddress((void**)&beff,    g_beff);
    cudaGetSymbolAddress((void**)&pool,    g_pool);
    cudaGetSymbolAddress((void**)&dw,      g_dw);
    cudaGetSymbolAddress((void**)&attn,    g_attn);
    cudaGetSymbolAddress((void**)&acomb,   g_acomb);
    cudaGetSymbolAddress((void**)&low1,    g_low1);
    cudaGetSymbolAddress((void**)&low2,    g_low2);
    cudaGetSymbolAddress((void**)&xk,      g_xk);
    cudaGetSymbolAddress((void**)&yq,      g_yq);
    cudaGetSymbolAddress((void**)&bnx,     g_bnx);
    cudaGetSymbolAddress((void**)&bny,     g_bny);
    cudaGetSymbolAddress((void**)&bnpartA, g_bnpartA);
    cudaGetSymbolAddress((void**)&bnpartB, g_bnpartB);
    cudaGetSymbolAddress((void**)&U,       g_U);
    cudaGetSymbolAddress((void**)&V,       g_V);
    cudaGetSymbolAddress((void**)&M,       g_M);

    const long fB   = (long)QC_*HW_;
    const long dB   = (long)D96*HW_;
    const long cB   = (long)C48*HW_;
    const long lowB = (long)D96*PL_;
    const long lowC = (long)C48*PL_;

    {
        long n = (long)B_*D96*HW_;
        copy_slot0<<<(unsigned)((n+255)/256), 256>>>(x_in, feats);
    }

    for (int i=0;i<2;i++){
        const float* s4 = mkw_s + i*4;
        build_weight<<<(D96*D96+255)/256, 256>>>(mkw_w + (size_t)i*D96*D96*9,
                                                 mkw_wc + (size_t)i*D96*D96*9,
                                                 mkw_wh + (size_t)i*D96*D96*3,
                                                 mkw_wv + (size_t)i*D96*D96*3,
                                                 mkw_wa + (size_t)i*D96*D96*9,
                                                 s4, weff);
        build_bias<<<1, D96>>>(mkw_b + i*D96, mkw_bc + i*D96, mkw_bh + i*D96,
                               mkw_bv + i*D96, mkw_ba + i*D96, s4, beff);

        // ---- MKW conv3x3 via Winograd F(2x2,3x3): feats slot i -> bufA ----
        const float* xcur = feats + (size_t)i*D96*HW_;
        wino_wtrans<<<(D96*D96+255)/256, 256>>>(weff, D96, D96, U);
        wino_itrans<<<dim3(NT_/256, D96), 256>>>(xcur, fB, D96, V);
        conv1x1_kernel<<<dim3(NT_/512, D96/32, 16), 256>>>(
            V, (long)D96*NT_, D96, U, nullptr, M, (long)D96*NT_, D96, NT_,
            (long)D96*D96);
        wino_otrans<<<(D96*NT_+255)/256, 256>>>(M, beff, bufA, dB);

        // qkv 1x1 (full res)
        conv1x1_kernel<<<dim3(HW_/512, QC_/32, B_), 256>>>(
            bufA, dB, D96, dt_wqkv + (size_t)i*QC_*D96, dt_bqkv + i*QC_,
            qkvfull, fB, QC_, HW_, 0L);

        maxpool8<<<(B_*QC_*PL_+255)/256, 256>>>(qkvfull, pool);
        dwconv3x3<<<(B_*QC_*PL_+255)/256, 256>>>(pool, dt_wdw + (size_t)i*QC_*9,
                                                 dt_bdw + i*QC_, dw);
        rownorm<<<2*B_*HEADS*C48, 256>>>(dw);
        attn_kernel<<<(B_*HEADS*C48*C48+255)/256, 256>>>(dw, dt_temp + i*HEADS, attn);
        topk_combine<<<1, 192>>>(attn, dt_aw + i*4, acomb);
        av_gelu<<<(B_*HEADS*C48*PL_+255)/256, 256>>>(acomb, dw, low1);

        // proj 1x1 at low res (commutes with nearest upsample) -> low2 = z (low res)
        conv1x1_kernel<<<dim3((PL_+511)/512, D96/32, B_), 256>>>(
            low1, lowB, D96, dt_wprj + (size_t)i*D96*D96, dt_bprj + i*D96,
            low2, lowB, D96, PL_, 0L);

        float* slot_out = feats + (size_t)(i+1)*D96*HW_;

        // ---- EAF_HF (xk at low res; exact) ----
        conv1x1_kernel<<<dim3((PL_+511)/512, (C48+31)/32, B_), 256>>>(
            low2, lowB, D96, eh_wx + (size_t)i*C48*D96, nullptr, xk, lowC, C48, PL_, 0L);
        conv1x1_kernel<<<dim3(HW_/512, (C48+31)/32, B_), 256>>>(
            hf, dB, D96, eh_wy + (size_t)i*C48*D96, nullptr, yq, cB, C48, HW_, 0L);
        bn_low<<<C48, 256>>>(xk, bnx);
        bn_partial1<<<dim3(C48,16), 256>>>(yq, bnpartB);
        bn_final1<<<1, C48>>>(bnpartB, bny);
        eaf_blend_hf<<<dim3(HW_/256, B_), 256>>>(low2, hf, dB, xk, yq, bnx, bny,
                                                 slot_out, fB);

        // ---- EAF_LF (both full res) ----
        conv1x1_kernel<<<dim3(HW_/512, (C48+31)/32, B_), 256>>>(
            slot_out, fB, D96, el_wx + (size_t)i*C48*D96, nullptr, xk, cB, C48, HW_, 0L);
        conv1x1_kernel<<<dim3(HW_/512, (C48+31)/32, B_), 256>>>(
            lf, dB, D96, el_wy + (size_t)i*C48*D96, nullptr, yq, cB, C48, HW_, 0L);
        bn_partial1<<<dim3(C48,16), 256>>>(xk, bnpartA);
        bn_partial1<<<dim3(C48,16), 256>>>(yq, bnpartB);
        bn_final1<<<1, C48>>>(bnpartA, bnx);
        bn_final1<<<1, C48>>>(bnpartB, bny);
        eaf_blend<<<dim3(HW_/256, B_), 256>>>(slot_out, fB, lf, dB, xk, yq, bnx, bny,
                                              slot_out, fB);
    }

    // ---- CAB conv3x3 (IC=288) via Winograd ----
    wino_wtrans<<<(D96*QC_+255)/256, 256>>>(cab_w, D96, QC_, U);
    wino_itrans<<<dim3(NT_/256, QC_), 256>>>(feats, fB, QC_, V);
    conv1x1_kernel<<<dim3(NT_/512, D96/32, 16), 256>>>(
        V, (long)QC_*NT_, QC_, U, nullptr, M, (long)D96*NT_, D96, NT_,
        (long)D96*QC_);
    wino_otrans<<<(D96*NT_+255)/256, 256>>>(M, cab_b, out, dB);
}

// round 8
// speedup vs baseline: 1.6819x; 1.2025x over previous
#include <cuda_runtime.h>
#include <math.h>

// ---------------- problem constants ----------------
#define B_    2
#define D96   96
#define H_    192
#define W_    192
#define HW_   (H_*W_)        // 36864
#define HEADS 2
#define C48   48
#define HL_   24
#define WL_   24
#define PL_   (HL_*WL_)      // 576
#define QC_   288            // 3*D
#define TPD_  48             // winograd F(4,3) tiles per spatial dim
#define NT_   4608           // 48*48*2 tiles

// ---------------- scratch (static, no runtime alloc) ----------------
__device__ float g_feats  [(size_t)B_*QC_*HW_];
__device__ float g_qkvfull[(size_t)B_*QC_*HW_];
__device__ float g_bufA   [(size_t)B_*D96*HW_];
__device__ float g_weff   [D96*D96*9];
__device__ float g_beff   [D96];
__device__ float g_pool   [(size_t)B_*QC_*PL_];
__device__ float g_dw     [(size_t)B_*QC_*PL_];
__device__ float g_attn   [B_*HEADS*C48*C48];
__device__ float g_acomb  [B_*HEADS*C48*C48];
__device__ float g_low1   [(size_t)B_*D96*PL_];
__device__ float g_low2   [(size_t)B_*D96*PL_];
__device__ float g_xk     [(size_t)B_*C48*HW_];
__device__ float g_yq     [(size_t)B_*C48*HW_];
__device__ float g_bnx    [2*C48];
__device__ float g_bny    [2*C48];
__device__ float g_bnpartA[C48][16][2];
__device__ float g_bnpartB[C48][16][2];
// winograd F(4x4,3x3) scratch
__device__ float g_U      [(size_t)36*D96*QC_];          // 36 * 96 * 288
__device__ float g_V      [(size_t)36*QC_*NT_];          // 191 MB max
__device__ float g_M      [(size_t)36*D96*NT_];          // 64 MB

// ---------------- MKW effective weight ----------------
__global__ void build_weight(const float* __restrict__ w,  const float* __restrict__ wc,
                             const float* __restrict__ wh, const float* __restrict__ wv,
                             const float* __restrict__ wa, const float* __restrict__ s4,
                             float* __restrict__ weff) {
    int idx = blockIdx.x * blockDim.x + threadIdx.x;   // oc*96+ic
    if (idx >= D96*D96) return;
    const float s0=s4[0], s1=s4[1], s2=s4[2], s3=s4[3];
    float wcl[9], wal[9];
    float csum = 0.f;
    #pragma unroll
    for (int t=0;t<9;t++){ wcl[t]=wc[(size_t)idx*9+t]; csum+=wcl[t]; }
    #pragma unroll
    for (int t=0;t<9;t++){ wal[t]=wa[(size_t)idx*9+t]; }
    const int perm[9] = {3,0,1,6,4,2,7,8,5};
    float wh0=wh[(size_t)idx*3+0], wh1=wh[(size_t)idx*3+1], wh2=wh[(size_t)idx*3+2];
    float wv0=wv[(size_t)idx*3+0], wv1=wv[(size_t)idx*3+1], wv2=wv[(size_t)idx*3+2];
    #pragma unroll
    for (int t=0;t<9;t++){
        float wcd = wcl[t] - (t==4 ? csum : 0.f);
        float whd = 0.f;
        if (t==0) whd =  wh0; else if (t==3) whd =  wh1; else if (t==6) whd =  wh2;
        else if (t==2) whd = -wh0; else if (t==5) whd = -wh1; else if (t==8) whd = -wh2;
        float wvd = 0.f;
        if (t<3) wvd = (t==0?wv0:(t==1?wv1:wv2));
        else if (t>=6) wvd = -(t==6?wv0:(t==7?wv1:wv2));
        float wad = wal[t] - wal[perm[t]];
        weff[(size_t)idx*9+t] = w[(size_t)idx*9+t] + s0*wcd + s1*whd + s2*wvd + s3*wad;
    }
}

__global__ void build_bias(const float* b, const float* bc, const float* bh,
                           const float* bv, const float* ba, const float* s4,
                           float* beff) {
    int c = threadIdx.x;
    if (c >= D96) return;
    beff[c] = b[c] + s4[0]*bc[c] + s4[1]*bh[c] + s4[2]*bv[c] + s4[3]*ba[c];
}

// ---------------- Winograd F(4x4,3x3): weight transform U = G g G^T ----------------
// G = [[1/4,0,0],[-1/6,-1/6,-1/6],[-1/6,1/6,-1/6],[1/24,1/12,1/6],[1/24,-1/12,1/6],[0,0,1]]
// w: [OC][IC][9] -> U: [36][OC*IC]
__global__ void wino_wtrans(const float* __restrict__ w, int OC, int IC,
                            float* __restrict__ U) {
    int idx = blockIdx.x*blockDim.x + threadIdx.x;   // oc*IC + ic
    if (idx >= OC*IC) return;
    float g[9];
    #pragma unroll
    for (int t=0;t<9;t++) g[t] = w[(size_t)idx*9 + t];
    const float i6 = 1.f/6.f, i12 = 1.f/12.f, i24 = 1.f/24.f;
    float Gg[6][3];
    #pragma unroll
    for (int c=0;c<3;c++){
        float g0 = g[c], g1 = g[3+c], g2 = g[6+c];
        Gg[0][c] = 0.25f*g0;
        Gg[1][c] = -i6*(g0 + g1 + g2);
        Gg[2][c] =  i6*(-g0 + g1 - g2);
        Gg[3][c] =  i24*g0 + i12*g1 + i6*g2;
        Gg[4][c] =  i24*g0 - i12*g1 + i6*g2;
        Gg[5][c] =  g2;
    }
    long OI = (long)OC*IC;
    #pragma unroll
    for (int r=0;r<6;r++){
        float a = Gg[r][0], b = Gg[r][1], c2 = Gg[r][2];
        U[(long)(r*6+0)*OI + idx] = 0.25f*a;
        U[(long)(r*6+1)*OI + idx] = -i6*(a + b + c2);
        U[(long)(r*6+2)*OI + idx] =  i6*(-a + b - c2);
        U[(long)(r*6+3)*OI + idx] =  i24*a + i12*b + i6*c2;
        U[(long)(r*6+4)*OI + idx] =  i24*a - i12*b + i6*c2;
        U[(long)(r*6+5)*OI + idx] =  c2;
    }
}

// ---------------- Winograd F(4,3) input transform V = B^T d B ----------------
// B^T = [[4,0,-5,0,1,0],[0,-4,-4,1,1,0],[0,4,-4,-1,1,0],[0,-2,-1,2,1,0],[0,2,-1,-2,1,0],[0,4,0,-5,0,1]]
// in: [B][IC][192][192] (batch stride inB) -> V: [36][IC][NT_]
__global__ void wino_itrans(const float* __restrict__ in, long inB, int IC,
                            float* __restrict__ V) {
    int n  = blockIdx.x*blockDim.x + threadIdx.x;   // 0..NT_-1 (NT_ % 256 == 0)
    int ic = blockIdx.y;
    int b   = n / (NT_/B_);
    int loc = n % (NT_/B_);
    int ty = loc / TPD_, tx = loc % TPD_;
    const float* src = in + (long)b*inB + (long)ic*HW_;
    int h0 = 4*ty - 1, w0 = 4*tx - 1;
    float d[6][6];
    #pragma unroll
    for (int r=0;r<6;r++){
        int hh = h0 + r;
        bool hok = (hh >= 0 && hh < H_);
        #pragma unroll
        for (int c=0;c<6;c++){
            int ww = w0 + c;
            d[r][c] = (hok && ww >= 0 && ww < W_) ? src[hh*W_ + ww] : 0.f;
        }
    }
    float t[6][6];
    #pragma unroll
    for (int c=0;c<6;c++){
        float d0=d[0][c], d1=d[1][c], d2=d[2][c], d3=d[3][c], d4=d[4][c], d5=d[5][c];
        t[0][c] =  4.f*d0 - 5.f*d2 + d4;
        t[1][c] = -4.f*d1 - 4.f*d2 + d3 + d4;
        t[2][c] =  4.f*d1 - 4.f*d2 - d3 + d4;
        t[3][c] = -2.f*d1 -      d2 + 2.f*d3 + d4;
        t[4][c] =  2.f*d1 -      d2 - 2.f*d3 + d4;
        t[5][c] =  4.f*d1 - 5.f*d3 + d5;
    }
    long stride = (long)IC*NT_;
    long base = (long)ic*NT_ + n;
    #pragma unroll
    for (int r=0;r<6;r++){
        float t0=t[r][0], t1=t[r][1], t2=t[r][2], t3=t[r][3], t4=t[r][4], t5=t[r][5];
        V[(long)(r*6+0)*stride + base] =  4.f*t0 - 5.f*t2 + t4;
        V[(long)(r*6+1)*stride + base] = -4.f*t1 - 4.f*t2 + t3 + t4;
        V[(long)(r*6+2)*stride + base] =  4.f*t1 - 4.f*t2 - t3 + t4;
        V[(long)(r*6+3)*stride + base] = -2.f*t1 -      t2 + 2.f*t3 + t4;
        V[(long)(r*6+4)*stride + base] =  2.f*t1 -      t2 - 2.f*t3 + t4;
        V[(long)(r*6+5)*stride + base] =  4.f*t1 - 5.f*t3 + t5;
    }
}

// ---------------- Winograd F(4,3) output transform Y = A^T m A + bias ----------------
// A^T = [[1,1,1,1,1,0],[0,1,-1,2,-2,0],[0,1,1,4,4,0],[0,1,-1,8,-8,1]]
// M: [36][96][NT_] -> out: [B][96][192][192] (batch stride outB)
__global__ void wino_otrans(const float* __restrict__ Mm, const float* __restrict__ bias,
                            float* __restrict__ out, long outB) {
    int idx = blockIdx.x*blockDim.x + threadIdx.x;   // oc*NT_ + n
    if (idx >= D96*NT_) return;
    int n  = idx % NT_;
    int oc = idx / NT_;
    float m[6][6];
    #pragma unroll
    for (int p=0;p<36;p++)
        m[p/6][p%6] = Mm[((long)p*D96 + oc)*NT_ + n];
    float t[4][6];
    #pragma unroll
    for (int c=0;c<6;c++){
        float m0=m[0][c], m1=m[1][c], m2=m[2][c], m3=m[3][c], m4=m[4][c], m5=m[5][c];
        t[0][c] = m0 + m1 + m2 + m3 + m4;
        t[1][c] = m1 - m2 + 2.f*m3 - 2.f*m4;
        t[2][c] = m1 + m2 + 4.f*m3 + 4.f*m4;
        t[3][c] = m1 - m2 + 8.f*m3 - 8.f*m4 + m5;
    }
    float bv = bias[oc];
    int b   = n / (NT_/B_);
    int loc = n % (NT_/B_);
    int ty = loc / TPD_, tx = loc % TPD_;
    float* dst = out + (long)b*outB + (long)oc*HW_ + (long)(4*ty)*W_ + 4*tx;
    #pragma unroll
    for (int r=0;r<4;r++){
        float t0=t[r][0], t1=t[r][1], t2=t[r][2], t3=t[r][3], t4=t[r][4], t5=t[r][5];
        float y0 = t0 + t1 + t2 + t3 + t4 + bv;
        float y1 = t1 - t2 + 2.f*t3 - 2.f*t4 + bv;
        float y2 = t1 + t2 + 4.f*t3 + 4.f*t4 + bv;
        float y3 = t1 - t2 + 8.f*t3 - 8.f*t4 + t5 + bv;
        float* row = dst + (long)r*W_;
        row[0]=y0; row[1]=y1; row[2]=y2; row[3]=y3;
    }
}

// ---------------- GEMM / 1x1 conv: 512px x 32oc block tile, 16px x 4oc / thread ----
// grid: (ceil(npix/512), ceil(OC/32), Z); block 256. IC % 16 == 0, npix % 4 == 0.
// z-batch: in += z*inB, out += z*outB, w += z*wB (wB=0 -> shared weights).
__global__ __launch_bounds__(256, 2)
void conv1x1_kernel(const float* __restrict__ in, long inB, int IC,
                    const float* __restrict__ w, const float* __restrict__ bias,
                    float* __restrict__ out, long outB, int OC, int npix, long wB) {
    const int tid  = threadIdx.x;
    const int lane = tid & 31;
    const int wy   = tid >> 5;
    const int p0   = blockIdx.x * 512;
    const int oc0  = blockIdx.y * 32;
    const int z    = blockIdx.z;

    __shared__ float xs[16][512];
    __shared__ float ws[16][32];

    float4 acc[4][4];
    #pragma unroll
    for (int j=0;j<4;j++)
        #pragma unroll
        for (int q=0;q<4;q++) acc[j][q] = make_float4(0.f,0.f,0.f,0.f);

    const float* inb = in + (long)z*inB;
    const float* wz  = w  + (long)z*wB;

    for (int c0=0; c0<IC; c0+=16) {
        #pragma unroll
        for (int s=0;s<8;s++){
            int li  = tid + s*256;
            int icl = li >> 7, pq = li & 127;
            int p = p0 + pq*4;
            float4 v = make_float4(0.f,0.f,0.f,0.f);
            if (p < npix)
                v = *reinterpret_cast<const float4*>(&inb[(long)(c0+icl)*npix + p]);
            *reinterpret_cast<float4*>(&xs[icl][pq*4]) = v;
        }
        #pragma unroll
        for (int s=0;s<2;s++){
            int li  = tid + s*256;
            int icl = li >> 5, ocl = li & 31;
            float v = 0.f;
            if (oc0+ocl < OC) v = wz[(long)(oc0+ocl)*IC + (c0+icl)];
            ws[icl][ocl] = v;
        }
        __syncthreads();
        #pragma unroll
        for (int ic=0; ic<16; ic++) {
            float4 xv[4];
            #pragma unroll
            for (int q=0;q<4;q++) xv[q] = *reinterpret_cast<const float4*>(&xs[ic][(q*32+lane)*4]);
            float4 wv = *reinterpret_cast<const float4*>(&ws[ic][wy*4]);
            #pragma unroll
            for (int q=0;q<4;q++){
                acc[0][q].x += xv[q].x*wv.x; acc[0][q].y += xv[q].y*wv.x; acc[0][q].z += xv[q].z*wv.x; acc[0][q].w += xv[q].w*wv.x;
                acc[1][q].x += xv[q].x*wv.y; acc[1][q].y += xv[q].y*wv.y; acc[1][q].z += xv[q].z*wv.y; acc[1][q].w += xv[q].w*wv.y;
                acc[2][q].x += xv[q].x*wv.z; acc[2][q].y += xv[q].y*wv.z; acc[2][q].z += xv[q].z*wv.z; acc[2][q].w += xv[q].w*wv.z;
                acc[3][q].x += xv[q].x*wv.w; acc[3][q].y += xv[q].y*wv.w; acc[3][q].z += xv[q].z*wv.w; acc[3][q].w += xv[q].w*wv.w;
            }
        }
        __syncthreads();
    }

    #pragma unroll
    for (int j=0;j<4;j++){
        int oc = oc0 + wy*4 + j;
        if (oc >= OC) continue;
        float bv = bias ? bias[oc] : 0.f;
        #pragma unroll
        for (int q=0;q<4;q++){
            int p = p0 + (q*32+lane)*4;
            if (p < npix){
                float4 r = acc[j][q];
                r.x += bv; r.y += bv; r.z += bv; r.w += bv;
                *reinterpret_cast<float4*>(&out[(long)z*outB + (long)oc*npix + p]) = r;
            }
        }
    }
}

// ---------------- 8x8 max pool ----------------
__global__ void maxpool8(const float* __restrict__ in, float* __restrict__ out) {
    int idx = blockIdx.x*blockDim.x + threadIdx.x;
    if (idx >= B_*QC_*PL_) return;
    int ow = idx % WL_;
    int oh = (idx / WL_) % HL_;
    int c  = (idx / PL_) % QC_;
    int b  =  idx / (PL_*QC_);
    const float* p = in + ((long)b*QC_ + c)*HW_ + (long)oh*8*W_ + ow*8;
    float m = -INFINITY;
    #pragma unroll
    for (int r=0;r<8;r++)
        #pragma unroll
        for (int cc=0;cc<8;cc++)
            m = fmaxf(m, p[r*W_ + cc]);
    out[idx] = m;
}

// ---------------- depthwise 3x3, pad=1, 24x24 ----------------
__global__ void dwconv3x3(const float* __restrict__ in, const float* __restrict__ w,
                          const float* __restrict__ bias, float* __restrict__ out) {
    int idx = blockIdx.x*blockDim.x + threadIdx.x;
    if (idx >= B_*QC_*PL_) return;
    int ow = idx % WL_;
    int oh = (idx / WL_) % HL_;
    int c  = (idx / PL_) % QC_;
    int b  =  idx / (PL_*QC_);
    const float* p = in + ((long)b*QC_ + c)*PL_;
    const float* wc = w + (long)c*9;
    float s = bias[c];
    #pragma unroll
    for (int dr=-1;dr<=1;dr++){
        int hh = oh+dr; if (hh<0||hh>=HL_) continue;
        #pragma unroll
        for (int dc=-1;dc<=1;dc++){
            int ww = ow+dc; if (ww<0||ww>=WL_) continue;
            s += wc[(dr+1)*3 + (dc+1)] * p[hh*WL_ + ww];
        }
    }
    out[idx] = s;
}

// ---------------- normalize q / k rows in place ----------------
__global__ void rownorm(float* dw) {
    int rid = blockIdx.x;
    int sel = rid / (B_*HEADS*C48);
    int rem = rid % (B_*HEADS*C48);
    int b   = rem / (HEADS*C48);
    int ch  = rem % (HEADS*C48);
    float* row = dw + ((long)b*QC_ + sel*D96 + ch)*PL_;
    __shared__ float sh[256];
    float s = 0.f;
    for (int i=threadIdx.x;i<PL_;i+=256){ float v=row[i]; s += v*v; }
    sh[threadIdx.x]=s; __syncthreads();
    for (int st=128;st>0;st>>=1){ if (threadIdx.x<st) sh[threadIdx.x]+=sh[threadIdx.x+st]; __syncthreads(); }
    float scale = 1.f / fmaxf(sqrtf(sh[0]), 1e-12f);
    for (int i=threadIdx.x;i<PL_;i+=256) row[i]*=scale;
}

// ---------------- attn = qn @ kn^T * temp ----------------
__global__ void attn_kernel(const float* __restrict__ dw, const float* __restrict__ temp,
                            float* __restrict__ attn) {
    int idx = blockIdx.x*blockDim.x + threadIdx.x;
    if (idx >= B_*HEADS*C48*C48) return;
    int j = idx % C48;
    int i = (idx / C48) % C48;
    int h = (idx / (C48*C48)) % HEADS;
    int b =  idx / (C48*C48*HEADS);
    const float* q = dw + ((long)b*QC_ +      h*C48 + i)*PL_;
    const float* k = dw + ((long)b*QC_ + D96 + h*C48 + j)*PL_;
    float s = 0.f;
    for (int n=0;n<PL_;n++) s += q[n]*k[n];
    attn[idx] = s * temp[h];
}

// ---------------- top-k threshold softmaxes, combined ----------------
__global__ void topk_combine(const float* __restrict__ attn, const float* __restrict__ aw,
                             float* __restrict__ acomb) {
    int r = threadIdx.x;
    if (r >= B_*HEADS*C48) return;
    const float* row = attn + (long)r*C48;
    float a[C48], srt[C48];
    for (int j=0;j<C48;j++){ a[j]=row[j]; srt[j]=a[j]; }
    for (int x=1;x<C48;x++){
        float key = srt[x]; int j = x-1;
        while (j>=0 && srt[j]<key){ srt[j+1]=srt[j]; j--; }
        srt[j+1]=key;
    }
    const int kks[4] = {24,32,36,38};
    float m = srt[0];
    float th[4], sm[4];
    #pragma unroll
    for (int l=0;l<4;l++){
        th[l] = srt[kks[l]-1];
        float s = 0.f;
        for (int j=0;j<C48;j++) if (a[j] >= th[l]) s += expf(a[j]-m);
        sm[l] = s;
    }
    float w0=aw[0], w1=aw[1], w2=aw[2], w3=aw[3];
    for (int j=0;j<C48;j++){
        float e = expf(a[j]-m);
        float o = 0.f;
        if (a[j] >= th[0]) o += w0*e/sm[0];
        if (a[j] >= th[1]) o += w1*e/sm[1];
        if (a[j] >= th[2]) o += w2*e/sm[2];
        if (a[j] >= th[3]) o += w3*e/sm[3];
        acomb[(long)r*C48 + j] = o;
    }
}

// ---------------- out = gelu(Acomb @ v) ----------------
__global__ void av_gelu(const float* __restrict__ acomb, const float* __restrict__ dw,
                        float* __restrict__ outlow) {
    int idx = blockIdx.x*blockDim.x + threadIdx.x;
    if (idx >= B_*HEADS*C48*PL_) return;
    int n = idx % PL_;
    int c = (idx / PL_) % C48;
    int h = (idx / (PL_*C48)) % HEADS;
    int b =  idx / (PL_*C48*HEADS);
    const float* arow = acomb + (((long)(b*HEADS+h))*C48 + c)*C48;
    const float* v = dw + ((long)b*QC_ + 2*D96 + h*C48)*PL_;
    float s = 0.f;
    #pragma unroll 4
    for (int d=0;d<C48;d++) s += arow[d] * v[(long)d*PL_ + n];
    float g = 0.5f * s * (1.f + erff(s * 0.70710678118654752440f));
    outlow[((long)b*D96 + h*C48 + c)*PL_ + n] = g;
}

// ---------------- BN stats: one full-res 48ch tensor, partials ----------------
__global__ void bn_partial1(const float* __restrict__ src, float (*part)[16][2]) {
    int c = blockIdx.x;
    int chunk = blockIdx.y;
    const float* base = src + ((long)(chunk>>3)*C48 + c)*HW_ + (long)(chunk & 7)*(HW_/8);
    float s = 0.f, s2 = 0.f;
    for (int i = threadIdx.x; i < HW_/8; i += 256){
        float v = base[i]; s += v; s2 += v*v;
    }
    __shared__ float sh[512];
    sh[threadIdx.x] = s; sh[256+threadIdx.x] = s2; __syncthreads();
    for (int st=128; st>0; st>>=1){
        if (threadIdx.x < st){ sh[threadIdx.x]+=sh[threadIdx.x+st]; sh[256+threadIdx.x]+=sh[256+threadIdx.x+st]; }
        __syncthreads();
    }
    if (threadIdx.x == 0){ part[c][chunk][0] = sh[0]; part[c][chunk][1] = sh[256]; }
}

__global__ void bn_final1(const float (*part)[16][2], float* dst) {
    int c = threadIdx.x;
    if (c >= C48) return;
    float s = 0.f, s2 = 0.f;
    #pragma unroll
    for (int k=0;k<16;k++){ s += part[c][k][0]; s2 += part[c][k][1]; }
    float N = (float)(B_*HW_);
    float m = s/N;
    float var = s2/N - m*m;
    dst[c]       = m;
    dst[C48+c]   = rsqrtf(fmaxf(var,0.f) + 1e-5f);
}

// ---------------- BN stats for low-res (exact equivalent of 64x-replicated) ----------------
__global__ void bn_low(const float* __restrict__ src, float* __restrict__ dst) {
    int c = blockIdx.x;
    float s = 0.f, s2 = 0.f;
    for (int i = threadIdx.x; i < B_*PL_; i += 256){
        int b = i / PL_, j = i % PL_;
        float v = src[((long)b*C48 + c)*PL_ + j];
        s += v; s2 += v*v;
    }
    __shared__ float sh[512];
    sh[threadIdx.x]=s; sh[256+threadIdx.x]=s2; __syncthreads();
    for (int st=128; st>0; st>>=1){
        if (threadIdx.x < st){ sh[threadIdx.x]+=sh[threadIdx.x+st]; sh[256+threadIdx.x]+=sh[256+threadIdx.x+st]; }
        __syncthreads();
    }
    if (threadIdx.x == 0){
        float N = (float)(B_*PL_);
        float m = sh[0]/N;
        float var = sh[256]/N - m*m;
        dst[c]     = m;
        dst[C48+c] = rsqrtf(fmaxf(var,0.f) + 1e-5f);
    }
}

// ---------------- EAF blend (both full-res) ----------------
__global__ void eaf_blend(const float* __restrict__ x, long xB,
                          const float* __restrict__ y, long yB,
                          const float* __restrict__ xk, const float* __restrict__ yq,
                          const float* __restrict__ bnx, const float* __restrict__ bny,
                          float* __restrict__ out, long outB) {
    int p = blockIdx.x*blockDim.x + threadIdx.x;
    int b = blockIdx.y;
    if (p >= HW_) return;
    long base = (long)b*C48*HW_ + p;
    float s = 0.f;
    for (int c=0;c<C48;c++){
        float a  = (xk[base + (long)c*HW_] - bnx[c]) * bnx[C48+c];
        float bb = (yq[base + (long)c*HW_] - bny[c]) * bny[C48+c];
        s += a*bb;
    }
    float sim = 1.f/(1.f + expf(-s));
    for (int c=0;c<D96;c++){
        float xv = x[(long)b*xB + (long)c*HW_ + p];
        float yv = y[(long)b*yB + (long)c*HW_ + p];
        out[(long)b*outB + (long)c*HW_ + p] = sim*xv + (1.f-sim)*yv;
    }
}

// ---------------- EAF blend HF variant: x and xk at low res ----------------
__global__ void eaf_blend_hf(const float* __restrict__ xlow,
                             const float* __restrict__ y, long yB,
                             const float* __restrict__ xklow,
                             const float* __restrict__ yq,
                             const float* __restrict__ bnx, const float* __restrict__ bny,
                             float* __restrict__ out, long outB) {
    int p = blockIdx.x*blockDim.x + threadIdx.x;
    int b = blockIdx.y;
    if (p >= HW_) return;
    int h = p / W_, w = p % W_;
    int lp = (h>>3)*WL_ + (w>>3);
    long basey = (long)b*C48*HW_ + p;
    float s = 0.f;
    for (int c=0;c<C48;c++){
        float a  = (xklow[((long)b*C48 + c)*PL_ + lp] - bnx[c]) * bnx[C48+c];
        float bb = (yq[basey + (long)c*HW_] - bny[c]) * bny[C48+c];
        s += a*bb;
    }
    float sim = 1.f/(1.f + expf(-s));
    for (int c=0;c<D96;c++){
        float xv = xlow[((long)b*D96 + c)*PL_ + lp];
        float yv = y[(long)b*yB + (long)c*HW_ + p];
        out[(long)b*outB + (long)c*HW_ + p] = sim*xv + (1.f-sim)*yv;
    }
}

// ---------------- copy input into feats slot 0 ----------------
__global__ void copy_slot0(const float* __restrict__ x, float* __restrict__ feats) {
    long idx = (long)blockIdx.x*blockDim.x + threadIdx.x;
    if (idx >= (long)B_*D96*HW_) return;
    long per = (long)D96*HW_;
    int b = idx / per;
    long r = idx % per;
    feats[(long)b*QC_*HW_ + r] = x[idx];
}

// ---------------- orchestration ----------------
extern "C" void kernel_launch(void* const* d_in, const int* in_sizes, int n_in,
                              void* d_out, int out_size) {
    const float* x_in   = (const float*)d_in[0];
    const float* hf     = (const float*)d_in[1];
    const float* lf     = (const float*)d_in[2];
    const float* mkw_w  = (const float*)d_in[3];
    const float* mkw_b  = (const float*)d_in[4];
    const float* mkw_wc = (const float*)d_in[5];
    const float* mkw_bc = (const float*)d_in[6];
    const float* mkw_wh = (const float*)d_in[7];
    const float* mkw_bh = (const float*)d_in[8];
    const float* mkw_wv = (const float*)d_in[9];
    const float* mkw_bv = (const float*)d_in[10];
    const float* mkw_wa = (const float*)d_in[11];
    const float* mkw_ba = (const float*)d_in[12];
    const float* mkw_s  = (const float*)d_in[13];
    const float* dt_temp= (const float*)d_in[14];
    const float* dt_wqkv= (const float*)d_in[15];
    const float* dt_bqkv= (const float*)d_in[16];
    const float* dt_wdw = (const float*)d_in[17];
    const float* dt_bdw = (const float*)d_in[18];
    const float* dt_wprj= (const float*)d_in[19];
    const float* dt_bprj= (const float*)d_in[20];
    const float* dt_aw  = (const float*)d_in[21];
    const float* eh_wx  = (const float*)d_in[22];
    const float* eh_wy  = (const float*)d_in[23];
    const float* el_wx  = (const float*)d_in[24];
    const float* el_wy  = (const float*)d_in[25];
    const float* cab_w  = (const float*)d_in[26];
    const float* cab_b  = (const float*)d_in[27];
    float* out = (float*)d_out;

    float *feats, *qkvfull, *bufA, *weff, *beff, *pool, *dw, *attn, *acomb,
          *low1, *low2, *xk, *yq, *bnx, *bny, *U, *V, *M;
    float (*bnpartA)[16][2]; float (*bnpartB)[16][2];
    cudaGetSymbolAddress((void**)&feats,   g_feats);
    cudaGetSymbolAddress((void**)&qkvfull, g_qkvfull);
    cudaGetSymbolAddress((void**)&bufA,    g_bufA);
    cudaGetSymbolAddress((void**)&weff,    g_weff);
    cudaGetSymbolAddress((void**)&beff,    g_beff);
    cudaGetSymbolAddress((void**)&pool,    g_pool);
    cudaGetSymbolAddress((void**)&dw,      g_dw);
    cudaGetSymbolAddress((void**)&attn,    g_attn);
    cudaGetSymbolAddress((void**)&acomb,   g_acomb);
    cudaGetSymbolAddress((void**)&low1,    g_low1);
    cudaGetSymbolAddress((void**)&low2,    g_low2);
    cudaGetSymbolAddress((void**)&xk,      g_xk);
    cudaGetSymbolAddress((void**)&yq,      g_yq);
    cudaGetSymbolAddress((void**)&bnx,     g_bnx);
    cudaGetSymbolAddress((void**)&bny,     g_bny);
    cudaGetSymbolAddress((void**)&bnpartA, g_bnpartA);
    cudaGetSymbolAddress((void**)&bnpartB, g_bnpartB);
    cudaGetSymbolAddress((void**)&U,       g_U);
    cudaGetSymbolAddress((void**)&V,       g_V);
    cudaGetSymbolAddress((void**)&M,       g_M);

    const long fB   = (long)QC_*HW_;
    const long dB   = (long)D96*HW_;
    const long cB   = (long)C48*HW_;
    const long lowB = (long)D96*PL_;
    const long lowC = (long)C48*PL_;

    {
        long n = (long)B_*D96*HW_;
        copy_slot0<<<(unsigned)((n+255)/256), 256>>>(x_in, feats);
    }

    for (int i=0;i<2;i++){
        const float* s4 = mkw_s + i*4;
        build_weight<<<(D96*D96+255)/256, 256>>>(mkw_w + (size_t)i*D96*D96*9,
                                                 mkw_wc + (size_t)i*D96*D96*9,
                                                 mkw_wh + (size_t)i*D96*D96*3,
                                                 mkw_wv + (size_t)i*D96*D96*3,
                                                 mkw_wa + (size_t)i*D96*D96*9,
                                                 s4, weff);
        build_bias<<<1, D96>>>(mkw_b + i*D96, mkw_bc + i*D96, mkw_bh + i*D96,
                               mkw_bv + i*D96, mkw_ba + i*D96, s4, beff);

        // ---- MKW conv3x3 via Winograd F(4x4,3x3): feats slot i -> bufA ----
        const float* xcur = feats + (size_t)i*D96*HW_;
        wino_wtrans<<<(D96*D96+255)/256, 256>>>(weff, D96, D96, U);
        wino_itrans<<<dim3(NT_/256, D96), 256>>>(xcur, fB, D96, V);
        conv1x1_kernel<<<dim3(NT_/512, D96/32, 36), 256>>>(
            V, (long)D96*NT_, D96, U, nullptr, M, (long)D96*NT_, D96, NT_,
            (long)D96*D96);
        wino_otrans<<<(D96*NT_+255)/256, 256>>>(M, beff, bufA, dB);

        // qkv 1x1 (full res)
        conv1x1_kernel<<<dim3(HW_/512, QC_/32, B_), 256>>>(
            bufA, dB, D96, dt_wqkv + (size_t)i*QC_*D96, dt_bqkv + i*QC_,
            qkvfull, fB, QC_, HW_, 0L);

        maxpool8<<<(B_*QC_*PL_+255)/256, 256>>>(qkvfull, pool);
        dwconv3x3<<<(B_*QC_*PL_+255)/256, 256>>>(pool, dt_wdw + (size_t)i*QC_*9,
                                                 dt_bdw + i*QC_, dw);
        rownorm<<<2*B_*HEADS*C48, 256>>>(dw);
        attn_kernel<<<(B_*HEADS*C48*C48+255)/256, 256>>>(dw, dt_temp + i*HEADS, attn);
        topk_combine<<<1, 192>>>(attn, dt_aw + i*4, acomb);
        av_gelu<<<(B_*HEADS*C48*PL_+255)/256, 256>>>(acomb, dw, low1);

        // proj 1x1 at low res (commutes with nearest upsample) -> low2 = z (low res)
        conv1x1_kernel<<<dim3((PL_+511)/512, D96/32, B_), 256>>>(
            low1, lowB, D96, dt_wprj + (size_t)i*D96*D96, dt_bprj + i*D96,
            low2, lowB, D96, PL_, 0L);

        float* slot_out = feats + (size_t)(i+1)*D96*HW_;

        // ---- EAF_HF (xk at low res; exact) ----
        conv1x1_kernel<<<dim3((PL_+511)/512, (C48+31)/32, B_), 256>>>(
            low2, lowB, D96, eh_wx + (size_t)i*C48*D96, nullptr, xk, lowC, C48, PL_, 0L);
        conv1x1_kernel<<<dim3(HW_/512, (C48+31)/32, B_), 256>>>(
            hf, dB, D96, eh_wy + (size_t)i*C48*D96, nullptr, yq, cB, C48, HW_, 0L);
        bn_low<<<C48, 256>>>(xk, bnx);
        bn_partial1<<<dim3(C48,16), 256>>>(yq, bnpartB);
        bn_final1<<<1, C48>>>(bnpartB, bny);
        eaf_blend_hf<<<dim3(HW_/256, B_), 256>>>(low2, hf, dB, xk, yq, bnx, bny,
                                                 slot_out, fB);

        // ---- EAF_LF (both full res) ----
        conv1x1_kernel<<<dim3(HW_/512, (C48+31)/32, B_), 256>>>(
            slot_out, fB, D96, el_wx + (size_t)i*C48*D96, nullptr, xk, cB, C48, HW_, 0L);
        conv1x1_kernel<<<dim3(HW_/512, (C48+31)/32, B_), 256>>>(
            lf, dB, D96, el_wy + (size_t)i*C48*D96, nullptr, yq, cB, C48, HW_, 0L);
        bn_partial1<<<dim3(C48,16), 256>>>(xk, bnpartA);
        bn_partial1<<<dim3(C48,16), 256>>>(yq, bnpartB);
        bn_final1<<<1, C48>>>(bnpartA, bnx);
        bn_final1<<<1, C48>>>(bnpartB, bny);
        eaf_blend<<<dim3(HW_/256, B_), 256>>>(slot_out, fB, lf, dB, xk, yq, bnx, bny,
                                              slot_out, fB);
    }

    // ---- CAB conv3x3 (IC=288) via Winograd F(4,3) ----
    wino_wtrans<<<(D96*QC_+255)/256, 256>>>(cab_w, D96, QC_, U);
    wino_itrans<<<dim3(NT_/256, QC_), 256>>>(feats, fB, QC_, V);
    conv1x1_kernel<<<dim3(NT_/512, D96/32, 36), 256>>>(
        V, (long)QC_*NT_, QC_, U, nullptr, M, (long)D96*NT_, D96, NT_,
        (long)D96*QC_);
    wino_otrans<<<(D96*NT_+255)/256, 256>>>(M, cab_b, out, dB);
}